// round 1
// baseline (speedup 1.0000x reference)
#include <cuda_runtime.h>

// Problem constants
#define T_SEQ 2048
#define CDIM  512
#define BDIM  2
#define HNUM  8
#define HD    64
#define BT    (BDIM * T_SEQ)
#define KCONV 1536   // 3*CDIM

// ---------------- scratch (device globals; no allocation allowed) ----------
__device__ float g_xpad[BDIM * (T_SEQ + 2) * CDIM];
__device__ float g_wc  [3 * CDIM * CDIM];
__device__ float g_conv[BT * CDIM];
__device__ float g_x1  [BT * CDIM];
__device__ float g_qkv [BT * 3 * CDIM];
__device__ float g_attn[BT * CDIM];
__device__ float g_proj[BT * CDIM];
__device__ float g_x2  [BT * CDIM];
__device__ float g_ffnh[BT * 2 * CDIM];
__device__ float g_ffn2[BT * CDIM];

// ---------------- small prep kernels ---------------------------------------
__global__ void pad_kernel(const float* __restrict__ x, float* __restrict__ xpad) {
    int idx = blockIdx.x * blockDim.x + threadIdx.x;
    const int total = BDIM * (T_SEQ + 2) * CDIM;
    if (idx >= total) return;
    int c = idx % CDIM;
    int t = (idx / CDIM) % (T_SEQ + 2);
    int b = idx / (CDIM * (T_SEQ + 2));
    xpad[idx] = (t < 2) ? 0.0f : x[((long long)b * T_SEQ + (t - 2)) * CDIM + c];
}

// conv_w is OIH [o][i][k]; build wc[(k*C+i)*C + o]
__global__ void wtr_kernel(const float* __restrict__ w, float* __restrict__ wc) {
    int idx = blockIdx.x * blockDim.x + threadIdx.x;
    const int total = 3 * CDIM * CDIM;
    if (idx >= total) return;
    int o = idx % CDIM;
    int i = (idx / CDIM) % CDIM;
    int k = idx / (CDIM * CDIM);
    wc[idx] = w[((long long)o * CDIM + i) * 3 + k];
}

// ---------------- fused residual add + LayerNorm ----------------------------
// out[row] = LN(a[row] + r[row]) * g + beta.  blockDim = 128, C = 512.
__global__ void add_ln_kernel(const float* __restrict__ a, const float* __restrict__ r,
                              const float* __restrict__ g, const float* __restrict__ be,
                              float* __restrict__ out) {
    __shared__ float sh[4];
    int row = blockIdx.x;
    int tid = threadIdx.x;
    const float4 va = ((const float4*)(a + (long long)row * CDIM))[tid];
    const float4 vr = ((const float4*)(r + (long long)row * CDIM))[tid];
    float x0 = va.x + vr.x, x1 = va.y + vr.y, x2 = va.z + vr.z, x3 = va.w + vr.w;

    float s = x0 + x1 + x2 + x3;
    #pragma unroll
    for (int o = 16; o; o >>= 1) s += __shfl_xor_sync(0xffffffffu, s, o);
    if ((tid & 31) == 0) sh[tid >> 5] = s;
    __syncthreads();
    float mean = (sh[0] + sh[1] + sh[2] + sh[3]) * (1.0f / CDIM);
    __syncthreads();

    float d0 = x0 - mean, d1 = x1 - mean, d2 = x2 - mean, d3 = x3 - mean;
    float ss = d0 * d0 + d1 * d1 + d2 * d2 + d3 * d3;
    #pragma unroll
    for (int o = 16; o; o >>= 1) ss += __shfl_xor_sync(0xffffffffu, ss, o);
    if ((tid & 31) == 0) sh[tid >> 5] = ss;
    __syncthreads();
    float var = (sh[0] + sh[1] + sh[2] + sh[3]) * (1.0f / CDIM);
    float rs = rsqrtf(var + 1e-5f);

    float4 vg = ((const float4*)g)[tid];
    float4 vb = ((const float4*)be)[tid];
    float4 o4;
    o4.x = d0 * rs * vg.x + vb.x;
    o4.y = d1 * rs * vg.y + vb.y;
    o4.z = d2 * rs * vg.z + vb.z;
    o4.w = d3 * rs * vg.w + vb.w;
    ((float4*)(out + (long long)row * CDIM))[tid] = o4;
}

// ---------------- generic tiled SGEMM ---------------------------------------
// C[M,N] = A[M,K] @ B[K,N] (+bias, +relu).  128x128 blocktile, BK=16,
// 256 threads, 8x8 per-thread microtile. M,N multiples of 128; K of 16.
// ACT: 1 = +bias, 2 = relu(+bias).
template <int ACT>
__global__ __launch_bounds__(256, 2)
void sgemm_kernel(const float* __restrict__ A, int lda, long long strideA,
                  const float* __restrict__ B, int ldb,
                  float* __restrict__ C, int ldc, long long strideC,
                  int K, const float* __restrict__ bias) {
    A += (long long)blockIdx.z * strideA;
    C += (long long)blockIdx.z * strideC;

    __shared__ float As[16][132];  // transposed A tile, padded
    __shared__ float Bs[16][128];

    const int tid = threadIdx.x;
    const int tx = tid & 15;
    const int ty = tid >> 4;

    float acc[8][8];
    #pragma unroll
    for (int i = 0; i < 8; i++)
        #pragma unroll
        for (int j = 0; j < 8; j++) acc[i][j] = 0.0f;

    const int rowA = tid >> 2;      // 0..63
    const int colA4 = tid & 3;      // 0..3  (16 K-cols / 4)
    const int rowB = tid >> 5;      // 0..7
    const int colB4 = tid & 31;     // 0..31 (128 N-cols / 4)

    const float* Aptr = A + ((long long)blockIdx.y * 128 + rowA) * lda + colA4 * 4;
    const float* Bptr = B + (long long)rowB * ldb + (long long)blockIdx.x * 128 + colB4 * 4;

    for (int kt = 0; kt < K; kt += 16) {
        float4 a0 = *(const float4*)(Aptr + kt);
        float4 a1 = *(const float4*)(Aptr + 64LL * lda + kt);
        float4 b0 = *(const float4*)(Bptr + (long long)kt * ldb);
        float4 b1 = *(const float4*)(Bptr + (long long)(kt + 8) * ldb);

        As[colA4 * 4 + 0][rowA] = a0.x;
        As[colA4 * 4 + 1][rowA] = a0.y;
        As[colA4 * 4 + 2][rowA] = a0.z;
        As[colA4 * 4 + 3][rowA] = a0.w;
        As[colA4 * 4 + 0][rowA + 64] = a1.x;
        As[colA4 * 4 + 1][rowA + 64] = a1.y;
        As[colA4 * 4 + 2][rowA + 64] = a1.z;
        As[colA4 * 4 + 3][rowA + 64] = a1.w;
        *(float4*)&Bs[rowB][colB4 * 4] = b0;
        *(float4*)&Bs[rowB + 8][colB4 * 4] = b1;
        __syncthreads();

        #pragma unroll
        for (int kk = 0; kk < 16; kk++) {
            float4 af0 = *(const float4*)&As[kk][ty * 8];
            float4 af1 = *(const float4*)&As[kk][ty * 8 + 4];
            float4 bf0 = *(const float4*)&Bs[kk][tx * 8];
            float4 bf1 = *(const float4*)&Bs[kk][tx * 8 + 4];
            float av[8] = {af0.x, af0.y, af0.z, af0.w, af1.x, af1.y, af1.z, af1.w};
            float bv[8] = {bf0.x, bf0.y, bf0.z, bf0.w, bf1.x, bf1.y, bf1.z, bf1.w};
            #pragma unroll
            for (int i = 0; i < 8; i++)
                #pragma unroll
                for (int j = 0; j < 8; j++) acc[i][j] += av[i] * bv[j];
        }
        __syncthreads();
    }

    const int row0 = blockIdx.y * 128 + ty * 8;
    const int col0 = blockIdx.x * 128 + tx * 8;
    float bvv[8];
    #pragma unroll
    for (int j = 0; j < 8; j++) bvv[j] = (ACT > 0) ? bias[col0 + j] : 0.0f;

    #pragma unroll
    for (int i = 0; i < 8; i++) {
        float v[8];
        #pragma unroll
        for (int j = 0; j < 8; j++) {
            float t = acc[i][j] + bvv[j];
            if (ACT == 2) t = fmaxf(t, 0.0f);
            v[j] = t;
        }
        float* cp = C + (long long)(row0 + i) * ldc + col0;
        *(float4*)(cp)     = make_float4(v[0], v[1], v[2], v[3]);
        *(float4*)(cp + 4) = make_float4(v[4], v[5], v[6], v[7]);
    }
}

// ---------------- flash attention (causal) ----------------------------------
// grid: (T/64, B*H), 256 threads. BQ=64, BK=32, hd=64, fp32, online softmax.
__global__ __launch_bounds__(256)
void flash_attn_kernel(const float* __restrict__ qkv, float* __restrict__ out) {
    __shared__ float Qs[64][68];
    __shared__ float Ks[32][68];
    __shared__ float Vs[32][68];
    __shared__ float Ss[64][36];

    const int qb = blockIdx.x;
    const int bh = blockIdx.y;
    const int b = bh >> 3, h = bh & 7;
    const int tid = threadIdx.x;
    const int tx = tid & 15;
    const int ty = tid >> 4;
    const long long rstride = 3 * CDIM;

    const float* qbase = qkv + ((long long)(b * T_SEQ + qb * 64)) * rstride + h * HD;
    #pragma unroll
    for (int i = 0; i < 4; i++) {
        int idx = tid + i * 256;      // 0..1023 : 64 rows x 16 float4
        int r = idx >> 4, c4 = idx & 15;
        *(float4*)&Qs[r][c4 * 4] = *(const float4*)(qbase + (long long)r * rstride + c4 * 4);
    }

    float o[4][4];
    float m[4], l[4];
    #pragma unroll
    for (int i = 0; i < 4; i++) {
        m[i] = -1e30f;
        l[i] = 0.0f;
        #pragma unroll
        for (int j = 0; j < 4; j++) o[i][j] = 0.0f;
    }

    const int ntiles = 2 * (qb + 1);
    for (int kb = 0; kb < ntiles; kb++) {
        const float* kbase = qkv + ((long long)(b * T_SEQ + kb * 32)) * rstride + CDIM + h * HD;
        const float* vbase = kbase + CDIM;
        #pragma unroll
        for (int i = 0; i < 2; i++) {
            int idx = tid + i * 256;  // 0..511 : 32 rows x 16 float4
            int r = idx >> 4, c4 = idx & 15;
            *(float4*)&Ks[r][c4 * 4] = *(const float4*)(kbase + (long long)r * rstride + c4 * 4);
            *(float4*)&Vs[r][c4 * 4] = *(const float4*)(vbase + (long long)r * rstride + c4 * 4);
        }
        __syncthreads();

        // S = Q @ K^T   (4 rows x 2 cols per thread)
        float s[4][2] = {{0, 0}, {0, 0}, {0, 0}, {0, 0}};
        #pragma unroll
        for (int d4 = 0; d4 < 16; d4++) {
            float4 k0 = *(const float4*)&Ks[tx * 2][d4 * 4];
            float4 k1 = *(const float4*)&Ks[tx * 2 + 1][d4 * 4];
            #pragma unroll
            for (int i = 0; i < 4; i++) {
                float4 q = *(const float4*)&Qs[ty * 4 + i][d4 * 4];
                s[i][0] += q.x * k0.x + q.y * k0.y + q.z * k0.z + q.w * k0.w;
                s[i][1] += q.x * k1.x + q.y * k1.y + q.z * k1.z + q.w * k1.w;
            }
        }

        // masked online softmax update
        #pragma unroll
        for (int i = 0; i < 4; i++) {
            int qt = qb * 64 + ty * 4 + i;
            int kt0 = kb * 32 + tx * 2;
            float s0 = (kt0     <= qt) ? s[i][0] * 0.125f : -1e30f;
            float s1 = (kt0 + 1 <= qt) ? s[i][1] * 0.125f : -1e30f;
            float mt = fmaxf(s0, s1);
            #pragma unroll
            for (int off = 8; off; off >>= 1)
                mt = fmaxf(mt, __shfl_xor_sync(0xffffffffu, mt, off, 16));
            float mnew = fmaxf(m[i], mt);
            float corr = __expf(m[i] - mnew);
            m[i] = mnew;
            float p0 = __expf(s0 - mnew);
            float p1 = __expf(s1 - mnew);
            Ss[ty * 4 + i][tx * 2]     = p0;
            Ss[ty * 4 + i][tx * 2 + 1] = p1;
            float ps = p0 + p1;
            #pragma unroll
            for (int off = 8; off; off >>= 1)
                ps += __shfl_xor_sync(0xffffffffu, ps, off, 16);
            l[i] = l[i] * corr + ps;
            #pragma unroll
            for (int j = 0; j < 4; j++) o[i][j] *= corr;
        }
        __syncthreads();

        // O += P @ V   (4 rows x 4 dcols per thread)
        #pragma unroll 8
        for (int kk = 0; kk < 32; kk++) {
            float4 v = *(const float4*)&Vs[kk][tx * 4];
            #pragma unroll
            for (int i = 0; i < 4; i++) {
                float p = Ss[ty * 4 + i][kk];
                o[i][0] += p * v.x;
                o[i][1] += p * v.y;
                o[i][2] += p * v.z;
                o[i][3] += p * v.w;
            }
        }
        __syncthreads();
    }

    #pragma unroll
    for (int i = 0; i < 4; i++) {
        float inv = 1.0f / l[i];
        int r = ty * 4 + i;
        float4 v = make_float4(o[i][0] * inv, o[i][1] * inv, o[i][2] * inv, o[i][3] * inv);
        *(float4*)(out + ((long long)(b * T_SEQ + qb * 64 + r)) * CDIM + h * HD + tx * 4) = v;
    }
}

// ---------------- launch -----------------------------------------------------
extern "C" void kernel_launch(void* const* d_in, const int* in_sizes, int n_in,
                              void* d_out, int out_size) {
    const float* x      = (const float*)d_in[0];
    const float* conv_w = (const float*)d_in[1];
    const float* conv_b = (const float*)d_in[2];
    const float* g1     = (const float*)d_in[3];
    const float* b1     = (const float*)d_in[4];
    const float* qkv_w  = (const float*)d_in[5];
    const float* qkv_b  = (const float*)d_in[6];
    const float* proj_w = (const float*)d_in[7];
    const float* proj_b = (const float*)d_in[8];
    const float* g2     = (const float*)d_in[9];
    const float* b2     = (const float*)d_in[10];
    const float* ffn_w1 = (const float*)d_in[11];
    const float* ffn_b1 = (const float*)d_in[12];
    const float* ffn_w2 = (const float*)d_in[13];
    const float* ffn_b2 = (const float*)d_in[14];
    const float* g3     = (const float*)d_in[15];
    const float* b3     = (const float*)d_in[16];
    float* out = (float*)d_out;

    float *xpad, *wc, *conv, *x1, *qkvb, *attn, *proj, *x2, *ffnh, *ffn2;
    cudaGetSymbolAddress((void**)&xpad, g_xpad);
    cudaGetSymbolAddress((void**)&wc,   g_wc);
    cudaGetSymbolAddress((void**)&conv, g_conv);
    cudaGetSymbolAddress((void**)&x1,   g_x1);
    cudaGetSymbolAddress((void**)&qkvb, g_qkv);
    cudaGetSymbolAddress((void**)&attn, g_attn);
    cudaGetSymbolAddress((void**)&proj, g_proj);
    cudaGetSymbolAddress((void**)&x2,   g_x2);
    cudaGetSymbolAddress((void**)&ffnh, g_ffnh);
    cudaGetSymbolAddress((void**)&ffn2, g_ffn2);

    // prep: padded input + transposed conv weights
    {
        int total = BDIM * (T_SEQ + 2) * CDIM;
        pad_kernel<<<(total + 255) / 256, 256>>>(x, xpad);
    }
    wtr_kernel<<<(3 * CDIM * CDIM + 255) / 256, 256>>>(conv_w, wc);

    // conv as GEMM: per batch, M=2048, N=512, K=1536, lda=C (overlapping rows)
    sgemm_kernel<1><<<dim3(4, 16, 2), 256>>>(
        xpad, CDIM, (long long)(T_SEQ + 2) * CDIM,
        wc, CDIM,
        conv, CDIM, (long long)T_SEQ * CDIM,
        KCONV, conv_b);

    // x1 = LN(x + conv)
    add_ln_kernel<<<BT, 128>>>(x, conv, g1, b1, x1);

    // qkv = x1 @ qkv_w + qkv_b : M=4096, N=1536, K=512
    sgemm_kernel<1><<<dim3(12, 32, 1), 256>>>(
        x1, CDIM, 0, qkv_w, 3 * CDIM, qkvb, 3 * CDIM, 0, CDIM, qkv_b);

    // causal flash attention
    flash_attn_kernel<<<dim3(T_SEQ / 64, BDIM * HNUM), 256>>>(qkvb, attn);

    // proj: M=4096, N=512, K=512
    sgemm_kernel<1><<<dim3(4, 32, 1), 256>>>(
        attn, CDIM, 0, proj_w, CDIM, proj, CDIM, 0, CDIM, proj_b);

    // x2 = LN(x1 + proj)
    add_ln_kernel<<<BT, 128>>>(x1, proj, g2, b2, x2);

    // ffn1: M=4096, N=1024, K=512, relu
    sgemm_kernel<2><<<dim3(8, 32, 1), 256>>>(
        x2, CDIM, 0, ffn_w1, 2 * CDIM, ffnh, 2 * CDIM, 0, CDIM, ffn_b1);

    // ffn2: M=4096, N=512, K=1024
    sgemm_kernel<1><<<dim3(4, 32, 1), 256>>>(
        ffnh, 2 * CDIM, 0, ffn_w2, CDIM, ffn2, CDIM, 0, 2 * CDIM, ffn_b2);

    // out = LN(x2 + ffn)
    add_ln_kernel<<<BT, 128>>>(x2, ffn2, g3, b3, out);
}

// round 2
// speedup vs baseline: 1.5395x; 1.5395x over previous
#include <cuda_runtime.h>
#include <cstdint>

// Problem constants
#define T_SEQ 2048
#define CDIM  512
#define BDIM  2
#define HNUM  8
#define HD    64
#define BT    (BDIM * T_SEQ)
#define KCONV 1536   // 3*CDIM

// ---------------- scratch (device globals; no allocation allowed) ----------
__device__ float g_xpad[BDIM * (T_SEQ + 2) * CDIM];
__device__ float g_wc  [3 * CDIM * CDIM];
__device__ float g_conv[BT * CDIM];
__device__ float g_x1  [BT * CDIM];
__device__ float g_qkv [BT * 3 * CDIM];
__device__ float g_attn[BT * CDIM];
__device__ float g_proj[BT * CDIM];
__device__ float g_x2  [BT * CDIM];
__device__ float g_ffnh[BT * 2 * CDIM];
__device__ float g_ffn2[BT * CDIM];

// ---------------- small prep kernels ---------------------------------------
__global__ void pad_kernel(const float* __restrict__ x, float* __restrict__ xpad) {
    int idx = blockIdx.x * blockDim.x + threadIdx.x;
    const int total = BDIM * (T_SEQ + 2) * CDIM;
    if (idx >= total) return;
    int c = idx % CDIM;
    int t = (idx / CDIM) % (T_SEQ + 2);
    int b = idx / (CDIM * (T_SEQ + 2));
    xpad[idx] = (t < 2) ? 0.0f : x[((long long)b * T_SEQ + (t - 2)) * CDIM + c];
}

// conv_w is OIH [o][i][k]; build wc[(k*C+i)*C + o]
__global__ void wtr_kernel(const float* __restrict__ w, float* __restrict__ wc) {
    int idx = blockIdx.x * blockDim.x + threadIdx.x;
    const int total = 3 * CDIM * CDIM;
    if (idx >= total) return;
    int o = idx % CDIM;
    int i = (idx / CDIM) % CDIM;
    int k = idx / (CDIM * CDIM);
    wc[idx] = w[((long long)o * CDIM + i) * 3 + k];
}

// ---------------- fused residual add + LayerNorm ----------------------------
__global__ void add_ln_kernel(const float* __restrict__ a, const float* __restrict__ r,
                              const float* __restrict__ g, const float* __restrict__ be,
                              float* __restrict__ out) {
    __shared__ float sh[4];
    int row = blockIdx.x;
    int tid = threadIdx.x;
    const float4 va = ((const float4*)(a + (long long)row * CDIM))[tid];
    const float4 vr = ((const float4*)(r + (long long)row * CDIM))[tid];
    float x0 = va.x + vr.x, x1 = va.y + vr.y, x2 = va.z + vr.z, x3 = va.w + vr.w;

    float s = x0 + x1 + x2 + x3;
    #pragma unroll
    for (int o = 16; o; o >>= 1) s += __shfl_xor_sync(0xffffffffu, s, o);
    if ((tid & 31) == 0) sh[tid >> 5] = s;
    __syncthreads();
    float mean = (sh[0] + sh[1] + sh[2] + sh[3]) * (1.0f / CDIM);
    __syncthreads();

    float d0 = x0 - mean, d1 = x1 - mean, d2 = x2 - mean, d3 = x3 - mean;
    float ss = d0 * d0 + d1 * d1 + d2 * d2 + d3 * d3;
    #pragma unroll
    for (int o = 16; o; o >>= 1) ss += __shfl_xor_sync(0xffffffffu, ss, o);
    if ((tid & 31) == 0) sh[tid >> 5] = ss;
    __syncthreads();
    float var = (sh[0] + sh[1] + sh[2] + sh[3]) * (1.0f / CDIM);
    float rs = rsqrtf(var + 1e-5f);

    float4 vg = ((const float4*)g)[tid];
    float4 vb = ((const float4*)be)[tid];
    float4 o4;
    o4.x = d0 * rs * vg.x + vb.x;
    o4.y = d1 * rs * vg.y + vb.y;
    o4.z = d2 * rs * vg.z + vb.z;
    o4.w = d3 * rs * vg.w + vb.w;
    ((float4*)(out + (long long)row * CDIM))[tid] = o4;
}

// ---------------- tf32 tensor-core GEMM --------------------------------------
// C[M,N] = A[M,K] @ B[K,N] (+bias, +relu).  128x128 blocktile, BK=16,
// 256 threads = 8 warps (2x4 MxN), warp tile 64x32 via m16n8k8 tf32 mma.
// Double-buffered smem, register prefetch. M,N mult of 128; K mult of 16.
// ACT: 1 = +bias, 2 = relu(+bias).

__device__ __forceinline__ uint32_t f2tf32(float f) {
    uint32_t u;
    asm("cvt.rna.tf32.f32 %0, %1;" : "=r"(u) : "f"(f));
    return u;
}

__device__ __forceinline__ void mma_tf32(float c[4], uint32_t a0, uint32_t a1,
                                         uint32_t a2, uint32_t a3,
                                         uint32_t b0, uint32_t b1) {
    asm volatile(
        "mma.sync.aligned.m16n8k8.row.col.f32.tf32.tf32.f32 "
        "{%0,%1,%2,%3}, {%4,%5,%6,%7}, {%8,%9}, {%0,%1,%2,%3};"
        : "+f"(c[0]), "+f"(c[1]), "+f"(c[2]), "+f"(c[3])
        : "r"(a0), "r"(a1), "r"(a2), "r"(a3), "r"(b0), "r"(b1));
}

#define SPAD 136  // 136 % 32 == 8 -> fragment loads map lanes to 32 distinct banks

template <int ACT>
__global__ __launch_bounds__(256, 2)
void tgemm_kernel(const float* __restrict__ A, int lda, long long strideA,
                  const float* __restrict__ B, int ldb,
                  float* __restrict__ C, int ldc, long long strideC,
                  int K, const float* __restrict__ bias) {
    A += (long long)blockIdx.z * strideA;
    C += (long long)blockIdx.z * strideC;

    __shared__ uint32_t As[2][16][SPAD];  // [k][m], tf32 bits
    __shared__ uint32_t Bs[2][16][SPAD];  // [k][n], tf32 bits

    const int tid = threadIdx.x;
    const int lane = tid & 31;
    const int warp = tid >> 5;
    const int warpM = warp >> 2;   // 0..1
    const int warpN = warp & 3;    // 0..3
    const int tg = lane & 3;       // thread-in-group
    const int gid = lane >> 2;     // group id

    float acc[4][4][4];
    #pragma unroll
    for (int i = 0; i < 4; i++)
        #pragma unroll
        for (int j = 0; j < 4; j++)
            #pragma unroll
            for (int q = 0; q < 4; q++) acc[i][j][q] = 0.0f;

    const int rowA = tid >> 2;    // 0..63
    const int colA4 = tid & 3;    // 0..3
    const int rowB = tid >> 5;    // 0..7
    const int colB4 = tid & 31;   // 0..31

    const float* Aptr = A + ((long long)blockIdx.y * 128 + rowA) * lda + colA4 * 4;
    const float* Bptr = B + (long long)rowB * ldb + (long long)blockIdx.x * 128 + colB4 * 4;

    // prefetch tile 0
    float4 pa0 = *(const float4*)(Aptr);
    float4 pa1 = *(const float4*)(Aptr + 64LL * lda);
    float4 pb0 = *(const float4*)(Bptr);
    float4 pb1 = *(const float4*)(Bptr + 8LL * ldb);

    // store tile 0 into buffer 0
    {
        As[0][colA4 * 4 + 0][rowA] = f2tf32(pa0.x);
        As[0][colA4 * 4 + 1][rowA] = f2tf32(pa0.y);
        As[0][colA4 * 4 + 2][rowA] = f2tf32(pa0.z);
        As[0][colA4 * 4 + 3][rowA] = f2tf32(pa0.w);
        As[0][colA4 * 4 + 0][rowA + 64] = f2tf32(pa1.x);
        As[0][colA4 * 4 + 1][rowA + 64] = f2tf32(pa1.y);
        As[0][colA4 * 4 + 2][rowA + 64] = f2tf32(pa1.z);
        As[0][colA4 * 4 + 3][rowA + 64] = f2tf32(pa1.w);
        Bs[0][rowB][colB4 * 4 + 0] = f2tf32(pb0.x);
        Bs[0][rowB][colB4 * 4 + 1] = f2tf32(pb0.y);
        Bs[0][rowB][colB4 * 4 + 2] = f2tf32(pb0.z);
        Bs[0][rowB][colB4 * 4 + 3] = f2tf32(pb0.w);
        Bs[0][rowB + 8][colB4 * 4 + 0] = f2tf32(pb1.x);
        Bs[0][rowB + 8][colB4 * 4 + 1] = f2tf32(pb1.y);
        Bs[0][rowB + 8][colB4 * 4 + 2] = f2tf32(pb1.z);
        Bs[0][rowB + 8][colB4 * 4 + 3] = f2tf32(pb1.w);
    }
    __syncthreads();

    const int ntile = K >> 4;
    int buf = 0;

    for (int t = 0; t < ntile; t++) {
        // prefetch next tile into registers
        if (t + 1 < ntile) {
            int kt = (t + 1) << 4;
            pa0 = *(const float4*)(Aptr + kt);
            pa1 = *(const float4*)(Aptr + 64LL * lda + kt);
            pb0 = *(const float4*)(Bptr + (long long)kt * ldb);
            pb1 = *(const float4*)(Bptr + (long long)(kt + 8) * ldb);
        }

        // compute on current buffer: two k8 steps
        #pragma unroll
        for (int ks = 0; ks < 2; ks++) {
            const int kb = ks * 8;
            uint32_t af[4][4], bf[4][2];
            #pragma unroll
            for (int mi = 0; mi < 4; mi++) {
                int m0 = warpM * 64 + mi * 16 + gid;
                af[mi][0] = As[buf][kb + tg][m0];
                af[mi][1] = As[buf][kb + tg][m0 + 8];
                af[mi][2] = As[buf][kb + tg + 4][m0];
                af[mi][3] = As[buf][kb + tg + 4][m0 + 8];
            }
            #pragma unroll
            for (int ni = 0; ni < 4; ni++) {
                int n0 = warpN * 32 + ni * 8 + gid;
                bf[ni][0] = Bs[buf][kb + tg][n0];
                bf[ni][1] = Bs[buf][kb + tg + 4][n0];
            }
            #pragma unroll
            for (int mi = 0; mi < 4; mi++)
                #pragma unroll
                for (int ni = 0; ni < 4; ni++)
                    mma_tf32(acc[mi][ni], af[mi][0], af[mi][1], af[mi][2], af[mi][3],
                             bf[ni][0], bf[ni][1]);
        }

        // store prefetched tile into other buffer
        if (t + 1 < ntile) {
            int nb = buf ^ 1;
            As[nb][colA4 * 4 + 0][rowA] = f2tf32(pa0.x);
            As[nb][colA4 * 4 + 1][rowA] = f2tf32(pa0.y);
            As[nb][colA4 * 4 + 2][rowA] = f2tf32(pa0.z);
            As[nb][colA4 * 4 + 3][rowA] = f2tf32(pa0.w);
            As[nb][colA4 * 4 + 0][rowA + 64] = f2tf32(pa1.x);
            As[nb][colA4 * 4 + 1][rowA + 64] = f2tf32(pa1.y);
            As[nb][colA4 * 4 + 2][rowA + 64] = f2tf32(pa1.z);
            As[nb][colA4 * 4 + 3][rowA + 64] = f2tf32(pa1.w);
            Bs[nb][rowB][colB4 * 4 + 0] = f2tf32(pb0.x);
            Bs[nb][rowB][colB4 * 4 + 1] = f2tf32(pb0.y);
            Bs[nb][rowB][colB4 * 4 + 2] = f2tf32(pb0.z);
            Bs[nb][rowB][colB4 * 4 + 3] = f2tf32(pb0.w);
            Bs[nb][rowB + 8][colB4 * 4 + 0] = f2tf32(pb1.x);
            Bs[nb][rowB + 8][colB4 * 4 + 1] = f2tf32(pb1.y);
            Bs[nb][rowB + 8][colB4 * 4 + 2] = f2tf32(pb1.z);
            Bs[nb][rowB + 8][colB4 * 4 + 3] = f2tf32(pb1.w);
            __syncthreads();
            buf = nb;
        }
    }

    // epilogue
    const int mbase = blockIdx.y * 128 + warpM * 64;
    const int nbase = blockIdx.x * 128 + warpN * 32;
    #pragma unroll
    for (int ni = 0; ni < 4; ni++) {
        int c0 = nbase + ni * 8 + tg * 2;
        float bv0 = 0.0f, bv1 = 0.0f;
        if (ACT > 0) { bv0 = bias[c0]; bv1 = bias[c0 + 1]; }
        #pragma unroll
        for (int mi = 0; mi < 4; mi++) {
            int r0 = mbase + mi * 16 + gid;
            float v00 = acc[mi][ni][0] + bv0;
            float v01 = acc[mi][ni][1] + bv1;
            float v10 = acc[mi][ni][2] + bv0;
            float v11 = acc[mi][ni][3] + bv1;
            if (ACT == 2) {
                v00 = fmaxf(v00, 0.0f); v01 = fmaxf(v01, 0.0f);
                v10 = fmaxf(v10, 0.0f); v11 = fmaxf(v11, 0.0f);
            }
            *(float2*)(C + (long long)r0 * ldc + c0) = make_float2(v00, v01);
            *(float2*)(C + (long long)(r0 + 8) * ldc + c0) = make_float2(v10, v11);
        }
    }
}

// ---------------- flash attention (causal) ----------------------------------
__global__ __launch_bounds__(256)
void flash_attn_kernel(const float* __restrict__ qkv, float* __restrict__ out) {
    __shared__ float Qs[64][68];
    __shared__ float Ks[32][68];
    __shared__ float Vs[32][68];
    __shared__ float Ss[64][36];

    const int qb = blockIdx.x;
    const int bh = blockIdx.y;
    const int b = bh >> 3, h = bh & 7;
    const int tid = threadIdx.x;
    const int tx = tid & 15;
    const int ty = tid >> 4;
    const long long rstride = 3 * CDIM;

    const float* qbase = qkv + ((long long)(b * T_SEQ + qb * 64)) * rstride + h * HD;
    #pragma unroll
    for (int i = 0; i < 4; i++) {
        int idx = tid + i * 256;
        int r = idx >> 4, c4 = idx & 15;
        *(float4*)&Qs[r][c4 * 4] = *(const float4*)(qbase + (long long)r * rstride + c4 * 4);
    }

    float o[4][4];
    float m[4], l[4];
    #pragma unroll
    for (int i = 0; i < 4; i++) {
        m[i] = -1e30f;
        l[i] = 0.0f;
        #pragma unroll
        for (int j = 0; j < 4; j++) o[i][j] = 0.0f;
    }

    const int ntiles = 2 * (qb + 1);
    for (int kb = 0; kb < ntiles; kb++) {
        const float* kbase = qkv + ((long long)(b * T_SEQ + kb * 32)) * rstride + CDIM + h * HD;
        const float* vbase = kbase + CDIM;
        #pragma unroll
        for (int i = 0; i < 2; i++) {
            int idx = tid + i * 256;
            int r = idx >> 4, c4 = idx & 15;
            *(float4*)&Ks[r][c4 * 4] = *(const float4*)(kbase + (long long)r * rstride + c4 * 4);
            *(float4*)&Vs[r][c4 * 4] = *(const float4*)(vbase + (long long)r * rstride + c4 * 4);
        }
        __syncthreads();

        float s[4][2] = {{0, 0}, {0, 0}, {0, 0}, {0, 0}};
        #pragma unroll
        for (int d4 = 0; d4 < 16; d4++) {
            float4 k0 = *(const float4*)&Ks[tx * 2][d4 * 4];
            float4 k1 = *(const float4*)&Ks[tx * 2 + 1][d4 * 4];
            #pragma unroll
            for (int i = 0; i < 4; i++) {
                float4 q = *(const float4*)&Qs[ty * 4 + i][d4 * 4];
                s[i][0] += q.x * k0.x + q.y * k0.y + q.z * k0.z + q.w * k0.w;
                s[i][1] += q.x * k1.x + q.y * k1.y + q.z * k1.z + q.w * k1.w;
            }
        }

        #pragma unroll
        for (int i = 0; i < 4; i++) {
            int qt = qb * 64 + ty * 4 + i;
            int kt0 = kb * 32 + tx * 2;
            float s0 = (kt0     <= qt) ? s[i][0] * 0.125f : -1e30f;
            float s1 = (kt0 + 1 <= qt) ? s[i][1] * 0.125f : -1e30f;
            float mt = fmaxf(s0, s1);
            #pragma unroll
            for (int off = 8; off; off >>= 1)
                mt = fmaxf(mt, __shfl_xor_sync(0xffffffffu, mt, off, 16));
            float mnew = fmaxf(m[i], mt);
            float corr = __expf(m[i] - mnew);
            m[i] = mnew;
            float p0 = __expf(s0 - mnew);
            float p1 = __expf(s1 - mnew);
            Ss[ty * 4 + i][tx * 2]     = p0;
            Ss[ty * 4 + i][tx * 2 + 1] = p1;
            float ps = p0 + p1;
            #pragma unroll
            for (int off = 8; off; off >>= 1)
                ps += __shfl_xor_sync(0xffffffffu, ps, off, 16);
            l[i] = l[i] * corr + ps;
            #pragma unroll
            for (int j = 0; j < 4; j++) o[i][j] *= corr;
        }
        __syncthreads();

        #pragma unroll 8
        for (int kk = 0; kk < 32; kk++) {
            float4 v = *(const float4*)&Vs[kk][tx * 4];
            #pragma unroll
            for (int i = 0; i < 4; i++) {
                float p = Ss[ty * 4 + i][kk];
                o[i][0] += p * v.x;
                o[i][1] += p * v.y;
                o[i][2] += p * v.z;
                o[i][3] += p * v.w;
            }
        }
        __syncthreads();
    }

    #pragma unroll
    for (int i = 0; i < 4; i++) {
        float inv = 1.0f / l[i];
        int r = ty * 4 + i;
        float4 v = make_float4(o[i][0] * inv, o[i][1] * inv, o[i][2] * inv, o[i][3] * inv);
        *(float4*)(out + ((long long)(b * T_SEQ + qb * 64 + r)) * CDIM + h * HD + tx * 4) = v;
    }
}

// ---------------- launch -----------------------------------------------------
extern "C" void kernel_launch(void* const* d_in, const int* in_sizes, int n_in,
                              void* d_out, int out_size) {
    const float* x      = (const float*)d_in[0];
    const float* conv_w = (const float*)d_in[1];
    const float* conv_b = (const float*)d_in[2];
    const float* g1     = (const float*)d_in[3];
    const float* b1     = (const float*)d_in[4];
    const float* qkv_w  = (const float*)d_in[5];
    const float* qkv_b  = (const float*)d_in[6];
    const float* proj_w = (const float*)d_in[7];
    const float* proj_b = (const float*)d_in[8];
    const float* g2     = (const float*)d_in[9];
    const float* b2     = (const float*)d_in[10];
    const float* ffn_w1 = (const float*)d_in[11];
    const float* ffn_b1 = (const float*)d_in[12];
    const float* ffn_w2 = (const float*)d_in[13];
    const float* ffn_b2 = (const float*)d_in[14];
    const float* g3     = (const float*)d_in[15];
    const float* b3     = (const float*)d_in[16];
    float* out = (float*)d_out;

    float *xpad, *wc, *conv, *x1, *qkvb, *attn, *proj, *x2, *ffnh, *ffn2;
    cudaGetSymbolAddress((void**)&xpad, g_xpad);
    cudaGetSymbolAddress((void**)&wc,   g_wc);
    cudaGetSymbolAddress((void**)&conv, g_conv);
    cudaGetSymbolAddress((void**)&x1,   g_x1);
    cudaGetSymbolAddress((void**)&qkvb, g_qkv);
    cudaGetSymbolAddress((void**)&attn, g_attn);
    cudaGetSymbolAddress((void**)&proj, g_proj);
    cudaGetSymbolAddress((void**)&x2,   g_x2);
    cudaGetSymbolAddress((void**)&ffnh, g_ffnh);
    cudaGetSymbolAddress((void**)&ffn2, g_ffn2);

    {
        int total = BDIM * (T_SEQ + 2) * CDIM;
        pad_kernel<<<(total + 255) / 256, 256>>>(x, xpad);
    }
    wtr_kernel<<<(3 * CDIM * CDIM + 255) / 256, 256>>>(conv_w, wc);

    // conv as GEMM: per batch, M=2048, N=512, K=1536, lda=C (overlapping rows)
    tgemm_kernel<1><<<dim3(4, 16, 2), 256>>>(
        xpad, CDIM, (long long)(T_SEQ + 2) * CDIM,
        wc, CDIM,
        conv, CDIM, (long long)T_SEQ * CDIM,
        KCONV, conv_b);

    add_ln_kernel<<<BT, 128>>>(x, conv, g1, b1, x1);

    // qkv: M=4096, N=1536, K=512
    tgemm_kernel<1><<<dim3(12, 32, 1), 256>>>(
        x1, CDIM, 0, qkv_w, 3 * CDIM, qkvb, 3 * CDIM, 0, CDIM, qkv_b);

    flash_attn_kernel<<<dim3(T_SEQ / 64, BDIM * HNUM), 256>>>(qkvb, attn);

    // proj: M=4096, N=512, K=512
    tgemm_kernel<1><<<dim3(4, 32, 1), 256>>>(
        attn, CDIM, 0, proj_w, CDIM, proj, CDIM, 0, CDIM, proj_b);

    add_ln_kernel<<<BT, 128>>>(x1, proj, g2, b2, x2);

    // ffn1: M=4096, N=1024, K=512, relu
    tgemm_kernel<2><<<dim3(8, 32, 1), 256>>>(
        x2, CDIM, 0, ffn_w1, 2 * CDIM, ffnh, 2 * CDIM, 0, CDIM, ffn_b1);

    // ffn2: M=4096, N=512, K=1024
    tgemm_kernel<1><<<dim3(4, 32, 1), 256>>>(
        ffnh, 2 * CDIM, 0, ffn_w2, CDIM, ffn2, CDIM, 0, 2 * CDIM, ffn_b2);

    add_ln_kernel<<<BT, 128>>>(x2, ffn2, g3, b3, out);
}

// round 3
// speedup vs baseline: 2.9724x; 1.9307x over previous
#include <cuda_runtime.h>
#include <cstdint>

// Problem constants
#define T_SEQ 2048
#define CDIM  512
#define BDIM  2
#define HNUM  8
#define HD    64
#define BT    (BDIM * T_SEQ)
#define KCONV 1536   // 3*CDIM

// ---------------- scratch (device globals; no allocation allowed) ----------
__device__ float g_xpad[BDIM * (T_SEQ + 2) * CDIM];
__device__ float g_wc  [3 * CDIM * CDIM];
__device__ float g_conv[BT * CDIM];
__device__ float g_x1  [BT * CDIM];
__device__ float g_qkv [BT * 3 * CDIM];
__device__ float g_attn[BT * CDIM];
__device__ float g_proj[BT * CDIM];
__device__ float g_x2  [BT * CDIM];
__device__ float g_ffnh[BT * 2 * CDIM];
__device__ float g_ffn2[BT * CDIM];

// ---------------- small prep kernels ---------------------------------------
__global__ void pad_kernel(const float* __restrict__ x, float* __restrict__ xpad) {
    int idx = blockIdx.x * blockDim.x + threadIdx.x;
    const int total = BDIM * (T_SEQ + 2) * CDIM;
    if (idx >= total) return;
    int c = idx % CDIM;
    int t = (idx / CDIM) % (T_SEQ + 2);
    int b = idx / (CDIM * (T_SEQ + 2));
    xpad[idx] = (t < 2) ? 0.0f : x[((long long)b * T_SEQ + (t - 2)) * CDIM + c];
}

// conv_w is OIH [o][i][k]; build wc[(k*C+i)*C + o]
__global__ void wtr_kernel(const float* __restrict__ w, float* __restrict__ wc) {
    int idx = blockIdx.x * blockDim.x + threadIdx.x;
    const int total = 3 * CDIM * CDIM;
    if (idx >= total) return;
    int o = idx % CDIM;
    int i = (idx / CDIM) % CDIM;
    int k = idx / (CDIM * CDIM);
    wc[idx] = w[((long long)o * CDIM + i) * 3 + k];
}

// ---------------- fused residual add + LayerNorm ----------------------------
__global__ void add_ln_kernel(const float* __restrict__ a, const float* __restrict__ r,
                              const float* __restrict__ g, const float* __restrict__ be,
                              float* __restrict__ out) {
    __shared__ float sh[4];
    int row = blockIdx.x;
    int tid = threadIdx.x;
    const float4 va = ((const float4*)(a + (long long)row * CDIM))[tid];
    const float4 vr = ((const float4*)(r + (long long)row * CDIM))[tid];
    float x0 = va.x + vr.x, x1 = va.y + vr.y, x2 = va.z + vr.z, x3 = va.w + vr.w;

    float s = x0 + x1 + x2 + x3;
    #pragma unroll
    for (int o = 16; o; o >>= 1) s += __shfl_xor_sync(0xffffffffu, s, o);
    if ((tid & 31) == 0) sh[tid >> 5] = s;
    __syncthreads();
    float mean = (sh[0] + sh[1] + sh[2] + sh[3]) * (1.0f / CDIM);
    __syncthreads();

    float d0 = x0 - mean, d1 = x1 - mean, d2 = x2 - mean, d3 = x3 - mean;
    float ss = d0 * d0 + d1 * d1 + d2 * d2 + d3 * d3;
    #pragma unroll
    for (int o = 16; o; o >>= 1) ss += __shfl_xor_sync(0xffffffffu, ss, o);
    if ((tid & 31) == 0) sh[tid >> 5] = ss;
    __syncthreads();
    float var = (sh[0] + sh[1] + sh[2] + sh[3]) * (1.0f / CDIM);
    float rs = rsqrtf(var + 1e-5f);

    float4 vg = ((const float4*)g)[tid];
    float4 vb = ((const float4*)be)[tid];
    float4 o4;
    o4.x = d0 * rs * vg.x + vb.x;
    o4.y = d1 * rs * vg.y + vb.y;
    o4.z = d2 * rs * vg.z + vb.z;
    o4.w = d3 * rs * vg.w + vb.w;
    ((float4*)(out + (long long)row * CDIM))[tid] = o4;
}

// ---------------- tf32 mma helpers -------------------------------------------
__device__ __forceinline__ uint32_t f2tf32(float f) {
    uint32_t u;
    asm("cvt.rna.tf32.f32 %0, %1;" : "=r"(u) : "f"(f));
    return u;
}

__device__ __forceinline__ void mma_tf32(float c[4], uint32_t a0, uint32_t a1,
                                         uint32_t a2, uint32_t a3,
                                         uint32_t b0, uint32_t b1) {
    asm volatile(
        "mma.sync.aligned.m16n8k8.row.col.f32.tf32.tf32.f32 "
        "{%0,%1,%2,%3}, {%4,%5,%6,%7}, {%8,%9}, {%0,%1,%2,%3};"
        : "+f"(c[0]), "+f"(c[1]), "+f"(c[2]), "+f"(c[3])
        : "r"(a0), "r"(a1), "r"(a2), "r"(a3), "r"(b0), "r"(b1));
}

// ---------------- tf32 tensor-core GEMM --------------------------------------
#define SPAD 136

template <int ACT>
__global__ __launch_bounds__(256, 2)
void tgemm_kernel(const float* __restrict__ A, int lda, long long strideA,
                  const float* __restrict__ B, int ldb,
                  float* __restrict__ C, int ldc, long long strideC,
                  int K, const float* __restrict__ bias) {
    A += (long long)blockIdx.z * strideA;
    C += (long long)blockIdx.z * strideC;

    __shared__ uint32_t As[2][16][SPAD];
    __shared__ uint32_t Bs[2][16][SPAD];

    const int tid = threadIdx.x;
    const int lane = tid & 31;
    const int warp = tid >> 5;
    const int warpM = warp >> 2;
    const int warpN = warp & 3;
    const int tg = lane & 3;
    const int gid = lane >> 2;

    float acc[4][4][4];
    #pragma unroll
    for (int i = 0; i < 4; i++)
        #pragma unroll
        for (int j = 0; j < 4; j++)
            #pragma unroll
            for (int q = 0; q < 4; q++) acc[i][j][q] = 0.0f;

    const int rowA = tid >> 2;
    const int colA4 = tid & 3;
    const int rowB = tid >> 5;
    const int colB4 = tid & 31;

    const float* Aptr = A + ((long long)blockIdx.y * 128 + rowA) * lda + colA4 * 4;
    const float* Bptr = B + (long long)rowB * ldb + (long long)blockIdx.x * 128 + colB4 * 4;

    float4 pa0 = *(const float4*)(Aptr);
    float4 pa1 = *(const float4*)(Aptr + 64LL * lda);
    float4 pb0 = *(const float4*)(Bptr);
    float4 pb1 = *(const float4*)(Bptr + 8LL * ldb);

    {
        As[0][colA4 * 4 + 0][rowA] = f2tf32(pa0.x);
        As[0][colA4 * 4 + 1][rowA] = f2tf32(pa0.y);
        As[0][colA4 * 4 + 2][rowA] = f2tf32(pa0.z);
        As[0][colA4 * 4 + 3][rowA] = f2tf32(pa0.w);
        As[0][colA4 * 4 + 0][rowA + 64] = f2tf32(pa1.x);
        As[0][colA4 * 4 + 1][rowA + 64] = f2tf32(pa1.y);
        As[0][colA4 * 4 + 2][rowA + 64] = f2tf32(pa1.z);
        As[0][colA4 * 4 + 3][rowA + 64] = f2tf32(pa1.w);
        Bs[0][rowB][colB4 * 4 + 0] = f2tf32(pb0.x);
        Bs[0][rowB][colB4 * 4 + 1] = f2tf32(pb0.y);
        Bs[0][rowB][colB4 * 4 + 2] = f2tf32(pb0.z);
        Bs[0][rowB][colB4 * 4 + 3] = f2tf32(pb0.w);
        Bs[0][rowB + 8][colB4 * 4 + 0] = f2tf32(pb1.x);
        Bs[0][rowB + 8][colB4 * 4 + 1] = f2tf32(pb1.y);
        Bs[0][rowB + 8][colB4 * 4 + 2] = f2tf32(pb1.z);
        Bs[0][rowB + 8][colB4 * 4 + 3] = f2tf32(pb1.w);
    }
    __syncthreads();

    const int ntile = K >> 4;
    int buf = 0;

    for (int t = 0; t < ntile; t++) {
        if (t + 1 < ntile) {
            int kt = (t + 1) << 4;
            pa0 = *(const float4*)(Aptr + kt);
            pa1 = *(const float4*)(Aptr + 64LL * lda + kt);
            pb0 = *(const float4*)(Bptr + (long long)kt * ldb);
            pb1 = *(const float4*)(Bptr + (long long)(kt + 8) * ldb);
        }

        #pragma unroll
        for (int ks = 0; ks < 2; ks++) {
            const int kb = ks * 8;
            uint32_t af[4][4], bf[4][2];
            #pragma unroll
            for (int mi = 0; mi < 4; mi++) {
                int m0 = warpM * 64 + mi * 16 + gid;
                af[mi][0] = As[buf][kb + tg][m0];
                af[mi][1] = As[buf][kb + tg][m0 + 8];
                af[mi][2] = As[buf][kb + tg + 4][m0];
                af[mi][3] = As[buf][kb + tg + 4][m0 + 8];
            }
            #pragma unroll
            for (int ni = 0; ni < 4; ni++) {
                int n0 = warpN * 32 + ni * 8 + gid;
                bf[ni][0] = Bs[buf][kb + tg][n0];
                bf[ni][1] = Bs[buf][kb + tg + 4][n0];
            }
            #pragma unroll
            for (int mi = 0; mi < 4; mi++)
                #pragma unroll
                for (int ni = 0; ni < 4; ni++)
                    mma_tf32(acc[mi][ni], af[mi][0], af[mi][1], af[mi][2], af[mi][3],
                             bf[ni][0], bf[ni][1]);
        }

        if (t + 1 < ntile) {
            int nb = buf ^ 1;
            As[nb][colA4 * 4 + 0][rowA] = f2tf32(pa0.x);
            As[nb][colA4 * 4 + 1][rowA] = f2tf32(pa0.y);
            As[nb][colA4 * 4 + 2][rowA] = f2tf32(pa0.z);
            As[nb][colA4 * 4 + 3][rowA] = f2tf32(pa0.w);
            As[nb][colA4 * 4 + 0][rowA + 64] = f2tf32(pa1.x);
            As[nb][colA4 * 4 + 1][rowA + 64] = f2tf32(pa1.y);
            As[nb][colA4 * 4 + 2][rowA + 64] = f2tf32(pa1.z);
            As[nb][colA4 * 4 + 3][rowA + 64] = f2tf32(pa1.w);
            Bs[nb][rowB][colB4 * 4 + 0] = f2tf32(pb0.x);
            Bs[nb][rowB][colB4 * 4 + 1] = f2tf32(pb0.y);
            Bs[nb][rowB][colB4 * 4 + 2] = f2tf32(pb0.z);
            Bs[nb][rowB][colB4 * 4 + 3] = f2tf32(pb0.w);
            Bs[nb][rowB + 8][colB4 * 4 + 0] = f2tf32(pb1.x);
            Bs[nb][rowB + 8][colB4 * 4 + 1] = f2tf32(pb1.y);
            Bs[nb][rowB + 8][colB4 * 4 + 2] = f2tf32(pb1.z);
            Bs[nb][rowB + 8][colB4 * 4 + 3] = f2tf32(pb1.w);
            __syncthreads();
            buf = nb;
        }
    }

    const int mbase = blockIdx.y * 128 + warpM * 64;
    const int nbase = blockIdx.x * 128 + warpN * 32;
    #pragma unroll
    for (int ni = 0; ni < 4; ni++) {
        int c0 = nbase + ni * 8 + tg * 2;
        float bv0 = 0.0f, bv1 = 0.0f;
        if (ACT > 0) { bv0 = bias[c0]; bv1 = bias[c0 + 1]; }
        #pragma unroll
        for (int mi = 0; mi < 4; mi++) {
            int r0 = mbase + mi * 16 + gid;
            float v00 = acc[mi][ni][0] + bv0;
            float v01 = acc[mi][ni][1] + bv1;
            float v10 = acc[mi][ni][2] + bv0;
            float v11 = acc[mi][ni][3] + bv1;
            if (ACT == 2) {
                v00 = fmaxf(v00, 0.0f); v01 = fmaxf(v01, 0.0f);
                v10 = fmaxf(v10, 0.0f); v11 = fmaxf(v11, 0.0f);
            }
            *(float2*)(C + (long long)r0 * ldc + c0) = make_float2(v00, v01);
            *(float2*)(C + (long long)(r0 + 8) * ldc + c0) = make_float2(v10, v11);
        }
    }
}

// ---------------- tensor-core flash attention (causal) -----------------------
// grid: (T/64, B*H), 128 threads = 4 warps; each warp owns 16 q-rows.
// BQ=64, BK=64, hd=64. tf32 m16n8k8 for QK^T and PV, fp32 softmax in registers.
// V rows stored permuted by phi^-1 so P's C-fragment doubles as PV's A-fragment.
#define KSP 68   // Ks pad: fragment load banks = 4*gid + tg -> 32 distinct
#define VSP 72   // Vs pad: fragment load banks = 8*tg + gid -> 32 distinct

__global__ __launch_bounds__(128)
void flash_attn_tc_kernel(const float* __restrict__ qkv, float* __restrict__ out) {
    __shared__ uint32_t Ks[64][KSP];
    __shared__ uint32_t Vs[64][VSP];

    const int qb = (gridDim.x - 1) - blockIdx.x;   // heavy blocks first
    const int bh = blockIdx.y;
    const int b = bh >> 3, h = bh & 7;
    const int tid = threadIdx.x;
    const int lane = tid & 31;
    const int warp = tid >> 5;
    const int g = lane >> 2;     // group id (row within fragment)
    const int t = lane & 3;      // thread in group

    const long long rstride = 3 * CDIM;

    // Q fragments in registers (scaled by 1/sqrt(hd) = 0.125)
    const float* qptr = qkv + ((long long)(b * T_SEQ + qb * 64 + warp * 16)) * rstride + h * HD;
    uint32_t qf[8][4];
    #pragma unroll
    for (int ks = 0; ks < 8; ks++) {
        qf[ks][0] = f2tf32(0.125f * __ldg(qptr + (long long)g * rstride + ks * 8 + t));
        qf[ks][1] = f2tf32(0.125f * __ldg(qptr + (long long)(g + 8) * rstride + ks * 8 + t));
        qf[ks][2] = f2tf32(0.125f * __ldg(qptr + (long long)g * rstride + ks * 8 + t + 4));
        qf[ks][3] = f2tf32(0.125f * __ldg(qptr + (long long)(g + 8) * rstride + ks * 8 + t + 4));
    }

    float o[8][4];
    #pragma unroll
    for (int ni = 0; ni < 8; ni++)
        #pragma unroll
        for (int q = 0; q < 4; q++) o[ni][q] = 0.0f;
    float m0 = -1e30f, m1 = -1e30f, l0 = 0.0f, l1 = 0.0f;

    const int row0 = qb * 64 + warp * 16 + g;
    const int row1 = row0 + 8;

    for (int kb = 0; kb <= qb; kb++) {
        // --- load K, V tiles (V rows permuted within groups of 8) ---
        const float* kbase = qkv + ((long long)(b * T_SEQ + kb * 64)) * rstride + CDIM + h * HD;
        const float* vbase = kbase + CDIM;
        #pragma unroll
        for (int i = 0; i < 8; i++) {
            int idx = tid + i * 128;          // 0..1023 : 64 rows x 16 float4
            int r = idx >> 4, c4 = idx & 15;
            float4 kv = *(const float4*)(kbase + (long long)r * rstride + c4 * 4);
            Ks[r][c4 * 4 + 0] = f2tf32(kv.x);
            Ks[r][c4 * 4 + 1] = f2tf32(kv.y);
            Ks[r][c4 * 4 + 2] = f2tf32(kv.z);
            Ks[r][c4 * 4 + 3] = f2tf32(kv.w);
            float4 vv = *(const float4*)(vbase + (long long)r * rstride + c4 * 4);
            int pr = (r & 56) | ((r & 1) << 2) | ((r >> 1) & 3);  // phi^-1 within group of 8
            Vs[pr][c4 * 4 + 0] = f2tf32(vv.x);
            Vs[pr][c4 * 4 + 1] = f2tf32(vv.y);
            Vs[pr][c4 * 4 + 2] = f2tf32(vv.z);
            Vs[pr][c4 * 4 + 3] = f2tf32(vv.w);
        }
        __syncthreads();

        // --- S = Q @ K^T : 8 n-tiles x 8 k-steps ---
        float s[8][4];
        #pragma unroll
        for (int ni = 0; ni < 8; ni++) {
            s[ni][0] = s[ni][1] = s[ni][2] = s[ni][3] = 0.0f;
            #pragma unroll
            for (int ks = 0; ks < 8; ks++) {
                uint32_t b0 = Ks[ni * 8 + g][ks * 8 + t];
                uint32_t b1 = Ks[ni * 8 + g][ks * 8 + t + 4];
                mma_tf32(s[ni], qf[ks][0], qf[ks][1], qf[ks][2], qf[ks][3], b0, b1);
            }
        }

        // --- causal mask (diagonal tile only) ---
        if (kb == qb) {
            #pragma unroll
            for (int ni = 0; ni < 8; ni++) {
                int col = kb * 64 + ni * 8 + 2 * t;
                if (col > row0)     s[ni][0] = -1e30f;
                if (col + 1 > row0) s[ni][1] = -1e30f;
                if (col > row1)     s[ni][2] = -1e30f;
                if (col + 1 > row1) s[ni][3] = -1e30f;
            }
        }

        // --- online softmax (registers + quad shuffles) ---
        float mt0 = -1e30f, mt1 = -1e30f;
        #pragma unroll
        for (int ni = 0; ni < 8; ni++) {
            mt0 = fmaxf(mt0, fmaxf(s[ni][0], s[ni][1]));
            mt1 = fmaxf(mt1, fmaxf(s[ni][2], s[ni][3]));
        }
        mt0 = fmaxf(mt0, __shfl_xor_sync(0xffffffffu, mt0, 1));
        mt0 = fmaxf(mt0, __shfl_xor_sync(0xffffffffu, mt0, 2));
        mt1 = fmaxf(mt1, __shfl_xor_sync(0xffffffffu, mt1, 1));
        mt1 = fmaxf(mt1, __shfl_xor_sync(0xffffffffu, mt1, 2));

        float mn0 = fmaxf(m0, mt0), mn1 = fmaxf(m1, mt1);
        float corr0 = __expf(m0 - mn0), corr1 = __expf(m1 - mn1);
        m0 = mn0; m1 = mn1;

        float ps0 = 0.0f, ps1 = 0.0f;
        uint32_t pf[8][4];
        #pragma unroll
        for (int ni = 0; ni < 8; ni++) {
            float p0 = __expf(s[ni][0] - mn0);
            float p1 = __expf(s[ni][1] - mn0);
            float p2 = __expf(s[ni][2] - mn1);
            float p3 = __expf(s[ni][3] - mn1);
            ps0 += p0 + p1;
            ps1 += p2 + p3;
            // C-frag {c0,c1,c2,c3} -> A-frag {a0,a1,a2,a3} = {c0,c2,c1,c3}
            pf[ni][0] = f2tf32(p0);
            pf[ni][1] = f2tf32(p2);
            pf[ni][2] = f2tf32(p1);
            pf[ni][3] = f2tf32(p3);
        }
        ps0 += __shfl_xor_sync(0xffffffffu, ps0, 1);
        ps0 += __shfl_xor_sync(0xffffffffu, ps0, 2);
        ps1 += __shfl_xor_sync(0xffffffffu, ps1, 1);
        ps1 += __shfl_xor_sync(0xffffffffu, ps1, 2);
        l0 = l0 * corr0 + ps0;
        l1 = l1 * corr1 + ps1;

        #pragma unroll
        for (int ni = 0; ni < 8; ni++) {
            o[ni][0] *= corr0;
            o[ni][1] *= corr0;
            o[ni][2] *= corr1;
            o[ni][3] *= corr1;
        }

        // --- O += P @ V : 8 n-tiles (dims) x 8 k-steps (keys) ---
        #pragma unroll
        for (int ni = 0; ni < 8; ni++) {
            #pragma unroll
            for (int ks = 0; ks < 8; ks++) {
                uint32_t b0 = Vs[ks * 8 + t][ni * 8 + g];
                uint32_t b1 = Vs[ks * 8 + t + 4][ni * 8 + g];
                mma_tf32(o[ni], pf[ks][0], pf[ks][1], pf[ks][2], pf[ks][3], b0, b1);
            }
        }
        __syncthreads();
    }

    // --- epilogue: normalize + store ---
    float inv0 = 1.0f / l0, inv1 = 1.0f / l1;
    float* obase = out + ((long long)(b * T_SEQ)) * CDIM + h * HD;
    #pragma unroll
    for (int ni = 0; ni < 8; ni++) {
        int col = ni * 8 + 2 * t;
        *(float2*)(obase + (long long)row0 * CDIM + col) =
            make_float2(o[ni][0] * inv0, o[ni][1] * inv0);
        *(float2*)(obase + (long long)row1 * CDIM + col) =
            make_float2(o[ni][2] * inv1, o[ni][3] * inv1);
    }
}

// ---------------- launch -----------------------------------------------------
extern "C" void kernel_launch(void* const* d_in, const int* in_sizes, int n_in,
                              void* d_out, int out_size) {
    const float* x      = (const float*)d_in[0];
    const float* conv_w = (const float*)d_in[1];
    const float* conv_b = (const float*)d_in[2];
    const float* g1     = (const float*)d_in[3];
    const float* b1     = (const float*)d_in[4];
    const float* qkv_w  = (const float*)d_in[5];
    const float* qkv_b  = (const float*)d_in[6];
    const float* proj_w = (const float*)d_in[7];
    const float* proj_b = (const float*)d_in[8];
    const float* g2     = (const float*)d_in[9];
    const float* b2     = (const float*)d_in[10];
    const float* ffn_w1 = (const float*)d_in[11];
    const float* ffn_b1 = (const float*)d_in[12];
    const float* ffn_w2 = (const float*)d_in[13];
    const float* ffn_b2 = (const float*)d_in[14];
    const float* g3     = (const float*)d_in[15];
    const float* b3     = (const float*)d_in[16];
    float* out = (float*)d_out;

    float *xpad, *wc, *conv, *x1, *qkvb, *attn, *proj, *x2, *ffnh, *ffn2;
    cudaGetSymbolAddress((void**)&xpad, g_xpad);
    cudaGetSymbolAddress((void**)&wc,   g_wc);
    cudaGetSymbolAddress((void**)&conv, g_conv);
    cudaGetSymbolAddress((void**)&x1,   g_x1);
    cudaGetSymbolAddress((void**)&qkvb, g_qkv);
    cudaGetSymbolAddress((void**)&attn, g_attn);
    cudaGetSymbolAddress((void**)&proj, g_proj);
    cudaGetSymbolAddress((void**)&x2,   g_x2);
    cudaGetSymbolAddress((void**)&ffnh, g_ffnh);
    cudaGetSymbolAddress((void**)&ffn2, g_ffn2);

    {
        int total = BDIM * (T_SEQ + 2) * CDIM;
        pad_kernel<<<(total + 255) / 256, 256>>>(x, xpad);
    }
    wtr_kernel<<<(3 * CDIM * CDIM + 255) / 256, 256>>>(conv_w, wc);

    // conv as GEMM: per batch, M=2048, N=512, K=1536, lda=C (overlapping rows)
    tgemm_kernel<1><<<dim3(4, 16, 2), 256>>>(
        xpad, CDIM, (long long)(T_SEQ + 2) * CDIM,
        wc, CDIM,
        conv, CDIM, (long long)T_SEQ * CDIM,
        KCONV, conv_b);

    add_ln_kernel<<<BT, 128>>>(x, conv, g1, b1, x1);

    // qkv: M=4096, N=1536, K=512
    tgemm_kernel<1><<<dim3(12, 32, 1), 256>>>(
        x1, CDIM, 0, qkv_w, 3 * CDIM, qkvb, 3 * CDIM, 0, CDIM, qkv_b);

    // tensor-core causal flash attention
    flash_attn_tc_kernel<<<dim3(T_SEQ / 64, BDIM * HNUM), 128>>>(qkvb, attn);

    // proj: M=4096, N=512, K=512
    tgemm_kernel<1><<<dim3(4, 32, 1), 256>>>(
        attn, CDIM, 0, proj_w, CDIM, proj, CDIM, 0, CDIM, proj_b);

    add_ln_kernel<<<BT, 128>>>(x1, proj, g2, b2, x2);

    // ffn1: M=4096, N=1024, K=512, relu
    tgemm_kernel<2><<<dim3(8, 32, 1), 256>>>(
        x2, CDIM, 0, ffn_w1, 2 * CDIM, ffnh, 2 * CDIM, 0, CDIM, ffn_b1);

    // ffn2: M=4096, N=512, K=1024
    tgemm_kernel<1><<<dim3(4, 32, 1), 256>>>(
        ffnh, 2 * CDIM, 0, ffn_w2, CDIM, ffn2, CDIM, 0, 2 * CDIM, ffn_b2);

    add_ln_kernel<<<BT, 128>>>(x2, ffn2, g3, b3, out);
}

// round 4
// speedup vs baseline: 3.2723x; 1.1009x over previous
#include <cuda_runtime.h>
#include <cstdint>

// Problem constants
#define T_SEQ 2048
#define CDIM  512
#define BDIM  2
#define HNUM  8
#define HD    64
#define BT    (BDIM * T_SEQ)
#define KCONV 1536   // 3*CDIM

// ---------------- scratch (device globals; no allocation allowed) ----------
__device__ float g_xpad[BDIM * (T_SEQ + 2) * CDIM];
__device__ float g_wc  [3 * CDIM * CDIM];
__device__ float g_conv[BT * CDIM];
__device__ float g_x1  [BT * CDIM];
__device__ float g_qkv [BT * 3 * CDIM];
__device__ float g_attn[BT * CDIM];
__device__ float g_proj[BT * CDIM];
__device__ float g_x2  [BT * CDIM];
__device__ float g_ffnh[BT * 2 * CDIM];
__device__ float g_ffn2[BT * CDIM];

// ---------------- small prep kernels ---------------------------------------
__global__ void pad_kernel(const float* __restrict__ x, float* __restrict__ xpad) {
    int idx = blockIdx.x * blockDim.x + threadIdx.x;
    const int total = BDIM * (T_SEQ + 2) * CDIM;
    if (idx >= total) return;
    int c = idx % CDIM;
    int t = (idx / CDIM) % (T_SEQ + 2);
    int b = idx / (CDIM * (T_SEQ + 2));
    xpad[idx] = (t < 2) ? 0.0f : x[((long long)b * T_SEQ + (t - 2)) * CDIM + c];
}

// conv_w is OIH [o][i][k]; build wc[(k*C+i)*C + o]
__global__ void wtr_kernel(const float* __restrict__ w, float* __restrict__ wc) {
    int idx = blockIdx.x * blockDim.x + threadIdx.x;
    const int total = 3 * CDIM * CDIM;
    if (idx >= total) return;
    int o = idx % CDIM;
    int i = (idx / CDIM) % CDIM;
    int k = idx / (CDIM * CDIM);
    wc[idx] = w[((long long)o * CDIM + i) * 3 + k];
}

// ---------------- fused residual add + LayerNorm ----------------------------
__global__ void add_ln_kernel(const float* __restrict__ a, const float* __restrict__ r,
                              const float* __restrict__ g, const float* __restrict__ be,
                              float* __restrict__ out) {
    __shared__ float sh[4];
    int row = blockIdx.x;
    int tid = threadIdx.x;
    const float4 va = ((const float4*)(a + (long long)row * CDIM))[tid];
    const float4 vr = ((const float4*)(r + (long long)row * CDIM))[tid];
    float x0 = va.x + vr.x, x1 = va.y + vr.y, x2 = va.z + vr.z, x3 = va.w + vr.w;

    float s = x0 + x1 + x2 + x3;
    #pragma unroll
    for (int o = 16; o; o >>= 1) s += __shfl_xor_sync(0xffffffffu, s, o);
    if ((tid & 31) == 0) sh[tid >> 5] = s;
    __syncthreads();
    float mean = (sh[0] + sh[1] + sh[2] + sh[3]) * (1.0f / CDIM);
    __syncthreads();

    float d0 = x0 - mean, d1 = x1 - mean, d2 = x2 - mean, d3 = x3 - mean;
    float ss = d0 * d0 + d1 * d1 + d2 * d2 + d3 * d3;
    #pragma unroll
    for (int o = 16; o; o >>= 1) ss += __shfl_xor_sync(0xffffffffu, ss, o);
    if ((tid & 31) == 0) sh[tid >> 5] = ss;
    __syncthreads();
    float var = (sh[0] + sh[1] + sh[2] + sh[3]) * (1.0f / CDIM);
    float rs = rsqrtf(var + 1e-5f);

    float4 vg = ((const float4*)g)[tid];
    float4 vb = ((const float4*)be)[tid];
    float4 o4;
    o4.x = d0 * rs * vg.x + vb.x;
    o4.y = d1 * rs * vg.y + vb.y;
    o4.z = d2 * rs * vg.z + vb.z;
    o4.w = d3 * rs * vg.w + vb.w;
    ((float4*)(out + (long long)row * CDIM))[tid] = o4;
}

// ---------------- tf32 mma helpers -------------------------------------------
__device__ __forceinline__ void mma_tf32(float c[4], uint32_t a0, uint32_t a1,
                                         uint32_t a2, uint32_t a3,
                                         uint32_t b0, uint32_t b1) {
    asm volatile(
        "mma.sync.aligned.m16n8k8.row.col.f32.tf32.tf32.f32 "
        "{%0,%1,%2,%3}, {%4,%5,%6,%7}, {%8,%9}, {%0,%1,%2,%3};"
        : "+f"(c[0]), "+f"(c[1]), "+f"(c[2]), "+f"(c[3])
        : "r"(a0), "r"(a1), "r"(a2), "r"(a3), "r"(b0), "r"(b1));
}

#define CP16(dst, src) \
    asm volatile("cp.async.cg.shared.global [%0], [%1], 16;" :: "r"(dst), "l"(src))
#define CP_COMMIT() asm volatile("cp.async.commit_group;")
#define CP_WAIT(n)  asm volatile("cp.async.wait_group %0;" :: "n"(n))

// ---------------- tf32 tensor-core GEMM, cp.async 4-stage pipeline -----------
// C[M,N] = A[M,K] @ B[K,N] (+bias, +relu). 128x128 blocktile, BK=16, 256 thr,
// warp tile 64x32 (m16n8k8). A tile row-major [128][APAD], B tile [16][BPAD].
// Raw f32 bits fed to mma.tf32 (hw truncation). K multiple of 16, >= 48.
#define APAD 20    // (20g+t)%32 -> 32 distinct banks; 80B row = 16B aligned
#define BPAD 136   // (8t+g)%32 -> 32 distinct banks; 544B row = 16B aligned
#define GSTAGES 4
#define ASZ (128 * APAD)
#define BSZ (16 * BPAD)
#define GEMM_SMEM (GSTAGES * (ASZ + BSZ) * 4)

template <int ACT>
__global__ __launch_bounds__(256)
void tgemm_kernel(const float* __restrict__ A, int lda, long long strideA,
                  const float* __restrict__ B, int ldb,
                  float* __restrict__ C, int ldc, long long strideC,
                  int K, const float* __restrict__ bias) {
    A += (long long)blockIdx.z * strideA;
    C += (long long)blockIdx.z * strideC;

    extern __shared__ float sm[];
    float* As = sm;                       // GSTAGES * ASZ
    float* Bs = sm + GSTAGES * ASZ;       // GSTAGES * BSZ

    const int tid = threadIdx.x;
    const int lane = tid & 31;
    const int warp = tid >> 5;
    const int warpM = warp >> 2;
    const int warpN = warp & 3;
    const int tg = lane & 3;
    const int gid = lane >> 2;

    float acc[4][4][4];
    #pragma unroll
    for (int i = 0; i < 4; i++)
        #pragma unroll
        for (int j = 0; j < 4; j++)
            #pragma unroll
            for (int q = 0; q < 4; q++) acc[i][j][q] = 0.0f;

    const int rowA = tid >> 2;    // 0..63
    const int colA4 = tid & 3;    // 0..3
    const int rowB = tid >> 5;    // 0..7
    const int colB4 = tid & 31;   // 0..31

    const float* Aptr = A + ((long long)blockIdx.y * 128 + rowA) * lda + colA4 * 4;
    const float* Bptr = B + (long long)rowB * ldb + (long long)blockIdx.x * 128 + colB4 * 4;

    const uint32_t aDst = (uint32_t)__cvta_generic_to_shared(As) +
                          (rowA * APAD + colA4 * 4) * 4;
    const uint32_t bDst = (uint32_t)__cvta_generic_to_shared(Bs) +
                          (rowB * BPAD + colB4 * 4) * 4;

    const int ntile = K >> 4;
    int fetch = 0;

    // prologue: fill GSTAGES-1 stages
    #pragma unroll
    for (int p = 0; p < GSTAGES - 1; p++) {
        int kt = fetch << 4;
        uint32_t ad = aDst + (fetch % GSTAGES) * ASZ * 4;
        uint32_t bd = bDst + (fetch % GSTAGES) * BSZ * 4;
        CP16(ad, Aptr + kt);
        CP16(ad + 64 * APAD * 4, Aptr + 64LL * lda + kt);
        CP16(bd, Bptr + (long long)kt * ldb);
        CP16(bd + 8 * BPAD * 4, Bptr + (long long)(kt + 8) * ldb);
        CP_COMMIT();
        fetch++;
    }

    for (int t = 0; t < ntile; t++) {
        CP_WAIT(GSTAGES - 2);
        __syncthreads();

        // issue next stage into the buffer freed last iteration
        if (fetch < ntile) {
            int kt = fetch << 4;
            uint32_t ad = aDst + (fetch % GSTAGES) * ASZ * 4;
            uint32_t bd = bDst + (fetch % GSTAGES) * BSZ * 4;
            CP16(ad, Aptr + kt);
            CP16(ad + 64 * APAD * 4, Aptr + 64LL * lda + kt);
            CP16(bd, Bptr + (long long)kt * ldb);
            CP16(bd + 8 * BPAD * 4, Bptr + (long long)(kt + 8) * ldb);
        }
        CP_COMMIT();
        fetch++;

        const float* Ab = As + (t % GSTAGES) * ASZ;
        const float* Bb = Bs + (t % GSTAGES) * BSZ;

        #pragma unroll
        for (int ks = 0; ks < 2; ks++) {
            const int kb = ks * 8;
            uint32_t af[4][4], bf[4][2];
            #pragma unroll
            for (int mi = 0; mi < 4; mi++) {
                int m0 = warpM * 64 + mi * 16 + gid;
                af[mi][0] = __float_as_uint(Ab[m0 * APAD + kb + tg]);
                af[mi][1] = __float_as_uint(Ab[(m0 + 8) * APAD + kb + tg]);
                af[mi][2] = __float_as_uint(Ab[m0 * APAD + kb + tg + 4]);
                af[mi][3] = __float_as_uint(Ab[(m0 + 8) * APAD + kb + tg + 4]);
            }
            #pragma unroll
            for (int ni = 0; ni < 4; ni++) {
                int n0 = warpN * 32 + ni * 8 + gid;
                bf[ni][0] = __float_as_uint(Bb[(kb + tg) * BPAD + n0]);
                bf[ni][1] = __float_as_uint(Bb[(kb + tg + 4) * BPAD + n0]);
            }
            #pragma unroll
            for (int mi = 0; mi < 4; mi++)
                #pragma unroll
                for (int ni = 0; ni < 4; ni++)
                    mma_tf32(acc[mi][ni], af[mi][0], af[mi][1], af[mi][2], af[mi][3],
                             bf[ni][0], bf[ni][1]);
        }
        __syncthreads();
    }

    const int mbase = blockIdx.y * 128 + warpM * 64;
    const int nbase = blockIdx.x * 128 + warpN * 32;
    #pragma unroll
    for (int ni = 0; ni < 4; ni++) {
        int c0 = nbase + ni * 8 + tg * 2;
        float bv0 = 0.0f, bv1 = 0.0f;
        if (ACT > 0) { bv0 = bias[c0]; bv1 = bias[c0 + 1]; }
        #pragma unroll
        for (int mi = 0; mi < 4; mi++) {
            int r0 = mbase + mi * 16 + gid;
            float v00 = acc[mi][ni][0] + bv0;
            float v01 = acc[mi][ni][1] + bv1;
            float v10 = acc[mi][ni][2] + bv0;
            float v11 = acc[mi][ni][3] + bv1;
            if (ACT == 2) {
                v00 = fmaxf(v00, 0.0f); v01 = fmaxf(v01, 0.0f);
                v10 = fmaxf(v10, 0.0f); v11 = fmaxf(v11, 0.0f);
            }
            *(float2*)(C + (long long)r0 * ldc + c0) = make_float2(v00, v01);
            *(float2*)(C + (long long)(r0 + 8) * ldc + c0) = make_float2(v10, v11);
        }
    }
}

// ---------------- tensor-core flash attention (causal) -----------------------
// grid: (T/64, B*H), 128 threads = 4 warps; each warp owns 16 q-rows.
// Raw f32 bits into mma.tf32. V rows permuted so P's C-frag is PV's A-frag.
#define KSP 68
#define VSP 72

__global__ __launch_bounds__(128)
void flash_attn_tc_kernel(const float* __restrict__ qkv, float* __restrict__ out) {
    __shared__ uint32_t Ks[64][KSP];
    __shared__ uint32_t Vs[64][VSP];

    const int qb = (gridDim.x - 1) - blockIdx.x;   // heavy blocks first
    const int bh = blockIdx.y;
    const int b = bh >> 3, h = bh & 7;
    const int tid = threadIdx.x;
    const int lane = tid & 31;
    const int warp = tid >> 5;
    const int g = lane >> 2;
    const int t = lane & 3;

    const long long rstride = 3 * CDIM;

    const float* qptr = qkv + ((long long)(b * T_SEQ + qb * 64 + warp * 16)) * rstride + h * HD;
    uint32_t qf[8][4];
    #pragma unroll
    for (int ks = 0; ks < 8; ks++) {
        qf[ks][0] = __float_as_uint(0.125f * __ldg(qptr + (long long)g * rstride + ks * 8 + t));
        qf[ks][1] = __float_as_uint(0.125f * __ldg(qptr + (long long)(g + 8) * rstride + ks * 8 + t));
        qf[ks][2] = __float_as_uint(0.125f * __ldg(qptr + (long long)g * rstride + ks * 8 + t + 4));
        qf[ks][3] = __float_as_uint(0.125f * __ldg(qptr + (long long)(g + 8) * rstride + ks * 8 + t + 4));
    }

    float o[8][4];
    #pragma unroll
    for (int ni = 0; ni < 8; ni++)
        #pragma unroll
        for (int q = 0; q < 4; q++) o[ni][q] = 0.0f;
    float m0 = -1e30f, m1 = -1e30f, l0 = 0.0f, l1 = 0.0f;

    const int row0 = qb * 64 + warp * 16 + g;
    const int row1 = row0 + 8;

    for (int kb = 0; kb <= qb; kb++) {
        const float* kbase = qkv + ((long long)(b * T_SEQ + kb * 64)) * rstride + CDIM + h * HD;
        const float* vbase = kbase + CDIM;
        #pragma unroll
        for (int i = 0; i < 8; i++) {
            int idx = tid + i * 128;
            int r = idx >> 4, c4 = idx & 15;
            float4 kv = *(const float4*)(kbase + (long long)r * rstride + c4 * 4);
            Ks[r][c4 * 4 + 0] = __float_as_uint(kv.x);
            Ks[r][c4 * 4 + 1] = __float_as_uint(kv.y);
            Ks[r][c4 * 4 + 2] = __float_as_uint(kv.z);
            Ks[r][c4 * 4 + 3] = __float_as_uint(kv.w);
            float4 vv = *(const float4*)(vbase + (long long)r * rstride + c4 * 4);
            int pr = (r & 56) | ((r & 1) << 2) | ((r >> 1) & 3);
            Vs[pr][c4 * 4 + 0] = __float_as_uint(vv.x);
            Vs[pr][c4 * 4 + 1] = __float_as_uint(vv.y);
            Vs[pr][c4 * 4 + 2] = __float_as_uint(vv.z);
            Vs[pr][c4 * 4 + 3] = __float_as_uint(vv.w);
        }
        __syncthreads();

        float s[8][4];
        #pragma unroll
        for (int ni = 0; ni < 8; ni++) {
            s[ni][0] = s[ni][1] = s[ni][2] = s[ni][3] = 0.0f;
            #pragma unroll
            for (int ks = 0; ks < 8; ks++) {
                uint32_t b0 = Ks[ni * 8 + g][ks * 8 + t];
                uint32_t b1 = Ks[ni * 8 + g][ks * 8 + t + 4];
                mma_tf32(s[ni], qf[ks][0], qf[ks][1], qf[ks][2], qf[ks][3], b0, b1);
            }
        }

        if (kb == qb) {
            #pragma unroll
            for (int ni = 0; ni < 8; ni++) {
                int col = kb * 64 + ni * 8 + 2 * t;
                if (col > row0)     s[ni][0] = -1e30f;
                if (col + 1 > row0) s[ni][1] = -1e30f;
                if (col > row1)     s[ni][2] = -1e30f;
                if (col + 1 > row1) s[ni][3] = -1e30f;
            }
        }

        float mt0 = -1e30f, mt1 = -1e30f;
        #pragma unroll
        for (int ni = 0; ni < 8; ni++) {
            mt0 = fmaxf(mt0, fmaxf(s[ni][0], s[ni][1]));
            mt1 = fmaxf(mt1, fmaxf(s[ni][2], s[ni][3]));
        }
        mt0 = fmaxf(mt0, __shfl_xor_sync(0xffffffffu, mt0, 1));
        mt0 = fmaxf(mt0, __shfl_xor_sync(0xffffffffu, mt0, 2));
        mt1 = fmaxf(mt1, __shfl_xor_sync(0xffffffffu, mt1, 1));
        mt1 = fmaxf(mt1, __shfl_xor_sync(0xffffffffu, mt1, 2));

        float mn0 = fmaxf(m0, mt0), mn1 = fmaxf(m1, mt1);
        float corr0 = __expf(m0 - mn0), corr1 = __expf(m1 - mn1);
        m0 = mn0; m1 = mn1;

        float ps0 = 0.0f, ps1 = 0.0f;
        uint32_t pf[8][4];
        #pragma unroll
        for (int ni = 0; ni < 8; ni++) {
            float p0 = __expf(s[ni][0] - mn0);
            float p1 = __expf(s[ni][1] - mn0);
            float p2 = __expf(s[ni][2] - mn1);
            float p3 = __expf(s[ni][3] - mn1);
            ps0 += p0 + p1;
            ps1 += p2 + p3;
            pf[ni][0] = __float_as_uint(p0);
            pf[ni][1] = __float_as_uint(p2);
            pf[ni][2] = __float_as_uint(p1);
            pf[ni][3] = __float_as_uint(p3);
        }
        ps0 += __shfl_xor_sync(0xffffffffu, ps0, 1);
        ps0 += __shfl_xor_sync(0xffffffffu, ps0, 2);
        ps1 += __shfl_xor_sync(0xffffffffu, ps1, 1);
        ps1 += __shfl_xor_sync(0xffffffffu, ps1, 2);
        l0 = l0 * corr0 + ps0;
        l1 = l1 * corr1 + ps1;

        #pragma unroll
        for (int ni = 0; ni < 8; ni++) {
            o[ni][0] *= corr0;
            o[ni][1] *= corr0;
            o[ni][2] *= corr1;
            o[ni][3] *= corr1;
        }

        #pragma unroll
        for (int ni = 0; ni < 8; ni++) {
            #pragma unroll
            for (int ks = 0; ks < 8; ks++) {
                uint32_t b0 = Vs[ks * 8 + t][ni * 8 + g];
                uint32_t b1 = Vs[ks * 8 + t + 4][ni * 8 + g];
                mma_tf32(o[ni], pf[ks][0], pf[ks][1], pf[ks][2], pf[ks][3], b0, b1);
            }
        }
        __syncthreads();
    }

    float inv0 = 1.0f / l0, inv1 = 1.0f / l1;
    float* obase = out + ((long long)(b * T_SEQ)) * CDIM + h * HD;
    #pragma unroll
    for (int ni = 0; ni < 8; ni++) {
        int col = ni * 8 + 2 * t;
        *(float2*)(obase + (long long)row0 * CDIM + col) =
            make_float2(o[ni][0] * inv0, o[ni][1] * inv0);
        *(float2*)(obase + (long long)row1 * CDIM + col) =
            make_float2(o[ni][2] * inv1, o[ni][3] * inv1);
    }
}

// ---------------- launch -----------------------------------------------------
extern "C" void kernel_launch(void* const* d_in, const int* in_sizes, int n_in,
                              void* d_out, int out_size) {
    const float* x      = (const float*)d_in[0];
    const float* conv_w = (const float*)d_in[1];
    const float* conv_b = (const float*)d_in[2];
    const float* g1     = (const float*)d_in[3];
    const float* b1     = (const float*)d_in[4];
    const float* qkv_w  = (const float*)d_in[5];
    const float* qkv_b  = (const float*)d_in[6];
    const float* proj_w = (const float*)d_in[7];
    const float* proj_b = (const float*)d_in[8];
    const float* g2     = (const float*)d_in[9];
    const float* b2     = (const float*)d_in[10];
    const float* ffn_w1 = (const float*)d_in[11];
    const float* ffn_b1 = (const float*)d_in[12];
    const float* ffn_w2 = (const float*)d_in[13];
    const float* ffn_b2 = (const float*)d_in[14];
    const float* g3     = (const float*)d_in[15];
    const float* b3     = (const float*)d_in[16];
    float* out = (float*)d_out;

    float *xpad, *wc, *conv, *x1, *qkvb, *attn, *proj, *x2, *ffnh, *ffn2;
    cudaGetSymbolAddress((void**)&xpad, g_xpad);
    cudaGetSymbolAddress((void**)&wc,   g_wc);
    cudaGetSymbolAddress((void**)&conv, g_conv);
    cudaGetSymbolAddress((void**)&x1,   g_x1);
    cudaGetSymbolAddress((void**)&qkvb, g_qkv);
    cudaGetSymbolAddress((void**)&attn, g_attn);
    cudaGetSymbolAddress((void**)&proj, g_proj);
    cudaGetSymbolAddress((void**)&x2,   g_x2);
    cudaGetSymbolAddress((void**)&ffnh, g_ffnh);
    cudaGetSymbolAddress((void**)&ffn2, g_ffn2);

    static bool attr_done = false;
    if (!attr_done) {
        cudaFuncSetAttribute(tgemm_kernel<1>,
                             cudaFuncAttributeMaxDynamicSharedMemorySize, GEMM_SMEM);
        cudaFuncSetAttribute(tgemm_kernel<2>,
                             cudaFuncAttributeMaxDynamicSharedMemorySize, GEMM_SMEM);
        attr_done = true;
    }

    {
        int total = BDIM * (T_SEQ + 2) * CDIM;
        pad_kernel<<<(total + 255) / 256, 256>>>(x, xpad);
    }
    wtr_kernel<<<(3 * CDIM * CDIM + 255) / 256, 256>>>(conv_w, wc);

    // conv as GEMM: per batch, M=2048, N=512, K=1536, lda=C (overlapping rows)
    tgemm_kernel<1><<<dim3(4, 16, 2), 256, GEMM_SMEM>>>(
        xpad, CDIM, (long long)(T_SEQ + 2) * CDIM,
        wc, CDIM,
        conv, CDIM, (long long)T_SEQ * CDIM,
        KCONV, conv_b);

    add_ln_kernel<<<BT, 128>>>(x, conv, g1, b1, x1);

    // qkv: M=4096, N=1536, K=512
    tgemm_kernel<1><<<dim3(12, 32, 1), 256, GEMM_SMEM>>>(
        x1, CDIM, 0, qkv_w, 3 * CDIM, qkvb, 3 * CDIM, 0, CDIM, qkv_b);

    // tensor-core causal flash attention
    flash_attn_tc_kernel<<<dim3(T_SEQ / 64, BDIM * HNUM), 128>>>(qkvb, attn);

    // proj: M=4096, N=512, K=512
    tgemm_kernel<1><<<dim3(4, 32, 1), 256, GEMM_SMEM>>>(
        attn, CDIM, 0, proj_w, CDIM, proj, CDIM, 0, CDIM, proj_b);

    add_ln_kernel<<<BT, 128>>>(x1, proj, g2, b2, x2);

    // ffn1: M=4096, N=1024, K=512, relu
    tgemm_kernel<2><<<dim3(8, 32, 1), 256, GEMM_SMEM>>>(
        x2, CDIM, 0, ffn_w1, 2 * CDIM, ffnh, 2 * CDIM, 0, CDIM, ffn_b1);

    // ffn2: M=4096, N=512, K=1024
    tgemm_kernel<1><<<dim3(4, 32, 1), 256, GEMM_SMEM>>>(
        ffnh, 2 * CDIM, 0, ffn_w2, CDIM, ffn2, CDIM, 0, 2 * CDIM, ffn_b2);

    add_ln_kernel<<<BT, 128>>>(x2, ffn2, g3, b3, out);
}

// round 6
// speedup vs baseline: 4.3134x; 1.3181x over previous
#include <cuda_runtime.h>
#include <cuda_fp16.h>
#include <cstdint>

// Problem constants
#define T_SEQ 2048
#define CDIM  512
#define BDIM  2
#define HNUM  8
#define HD    64
#define BT    (BDIM * T_SEQ)

// ---------------- scratch (device globals; no allocation allowed) ----------
__device__ __half g_xpad [BDIM * (T_SEQ + 2) * CDIM];
__device__ __half g_wcT  [CDIM * 3 * CDIM];     // [o][k*512+i]
__device__ __half g_qkvT [3 * CDIM * CDIM];     // [1536][512]
__device__ __half g_projT[CDIM * CDIM];         // [512][512]
__device__ __half g_ffn1T[2 * CDIM * CDIM];     // [1024][512]
__device__ __half g_ffn2T[CDIM * 2 * CDIM];     // [512][1024]
__device__ __half g_x1h  [BT * CDIM];
__device__ __half g_x2h  [BT * CDIM];
__device__ __half g_attnh[BT * CDIM];
__device__ __half g_ffnhh[BT * 2 * CDIM];
__device__ float  g_conv [BT * CDIM];
__device__ float  g_x1   [BT * CDIM];
__device__ float  g_qkv  [BT * 3 * CDIM];
__device__ float  g_proj [BT * CDIM];
__device__ float  g_x2   [BT * CDIM];
__device__ float  g_ffn2 [BT * CDIM];

// ---------------- small prep kernels ---------------------------------------
__global__ void pad_kernel(const float* __restrict__ x, __half* __restrict__ xpad) {
    int idx = blockIdx.x * blockDim.x + threadIdx.x;
    const int total = BDIM * (T_SEQ + 2) * CDIM;
    if (idx >= total) return;
    int c = idx % CDIM;
    int t = (idx / CDIM) % (T_SEQ + 2);
    int b = idx / (CDIM * (T_SEQ + 2));
    float v = (t < 2) ? 0.0f : x[((long long)b * T_SEQ + (t - 2)) * CDIM + c];
    xpad[idx] = __float2half_rn(v);
}

// conv_w OIH [o][i][k] -> wcT[o][k*512+i]  (B^T for the conv GEMM)
__global__ void wconvT_kernel(const float* __restrict__ w, __half* __restrict__ outp) {
    int idx = blockIdx.x * blockDim.x + threadIdx.x;
    const int total = CDIM * 3 * CDIM;
    if (idx >= total) return;
    int o = idx / (3 * CDIM);
    int r = idx % (3 * CDIM);
    int k = r / CDIM;
    int i = r % CDIM;
    outp[idx] = __float2half_rn(w[((long long)o * CDIM + i) * 3 + k]);
}

// [K][N] fp32 -> [N][K] fp16 tiled transpose. blockDim (32,8), grid (N/32, K/32).
__global__ void transpose_kernel(const float* __restrict__ in, __half* __restrict__ outp,
                                 int K, int N) {
    __shared__ float tile[32][33];
    int bx = blockIdx.x * 32, by = blockIdx.y * 32;
    #pragma unroll
    for (int j = 0; j < 32; j += 8)
        tile[threadIdx.y + j][threadIdx.x] =
            in[(long long)(by + threadIdx.y + j) * N + bx + threadIdx.x];
    __syncthreads();
    #pragma unroll
    for (int j = 0; j < 32; j += 8)
        outp[(long long)(bx + threadIdx.y + j) * K + by + threadIdx.x] =
            __float2half_rn(tile[threadIdx.x][threadIdx.y + j]);
}

// ---------------- fused residual add + LayerNorm (dual fp32/fp16 out) -------
__global__ void add_ln_kernel(const float* __restrict__ a, const float* __restrict__ r,
                              const float* __restrict__ g, const float* __restrict__ be,
                              float* __restrict__ out, __half* __restrict__ outh) {
    __shared__ float sh[4];
    int row = blockIdx.x;
    int tid = threadIdx.x;
    const float4 va = ((const float4*)(a + (long long)row * CDIM))[tid];
    const float4 vr = ((const float4*)(r + (long long)row * CDIM))[tid];
    float x0 = va.x + vr.x, x1 = va.y + vr.y, x2 = va.z + vr.z, x3 = va.w + vr.w;

    float s = x0 + x1 + x2 + x3;
    #pragma unroll
    for (int o = 16; o; o >>= 1) s += __shfl_xor_sync(0xffffffffu, s, o);
    if ((tid & 31) == 0) sh[tid >> 5] = s;
    __syncthreads();
    float mean = (sh[0] + sh[1] + sh[2] + sh[3]) * (1.0f / CDIM);
    __syncthreads();

    float d0 = x0 - mean, d1 = x1 - mean, d2 = x2 - mean, d3 = x3 - mean;
    float ss = d0 * d0 + d1 * d1 + d2 * d2 + d3 * d3;
    #pragma unroll
    for (int o = 16; o; o >>= 1) ss += __shfl_xor_sync(0xffffffffu, ss, o);
    if ((tid & 31) == 0) sh[tid >> 5] = ss;
    __syncthreads();
    float var = (sh[0] + sh[1] + sh[2] + sh[3]) * (1.0f / CDIM);
    float rs = rsqrtf(var + 1e-5f);

    float4 vg = ((const float4*)g)[tid];
    float4 vb = ((const float4*)be)[tid];
    float4 o4;
    o4.x = d0 * rs * vg.x + vb.x;
    o4.y = d1 * rs * vg.y + vb.y;
    o4.z = d2 * rs * vg.z + vb.z;
    o4.w = d3 * rs * vg.w + vb.w;
    ((float4*)(out + (long long)row * CDIM))[tid] = o4;
    if (outh) {
        __half2 h0 = __floats2half2_rn(o4.x, o4.y);
        __half2 h1 = __floats2half2_rn(o4.z, o4.w);
        *(uint2*)(outh + (long long)row * CDIM + tid * 4) =
            make_uint2(*(uint32_t*)&h0, *(uint32_t*)&h1);
    }
}

// ---------------- mma helpers -------------------------------------------------
__device__ __forceinline__ void mma_f16(float c[4], uint32_t a0, uint32_t a1,
                                        uint32_t a2, uint32_t a3,
                                        uint32_t b0, uint32_t b1) {
    asm volatile(
        "mma.sync.aligned.m16n8k16.row.col.f32.f16.f16.f32 "
        "{%0,%1,%2,%3}, {%4,%5,%6,%7}, {%8,%9}, {%0,%1,%2,%3};"
        : "+f"(c[0]), "+f"(c[1]), "+f"(c[2]), "+f"(c[3])
        : "r"(a0), "r"(a1), "r"(a2), "r"(a3), "r"(b0), "r"(b1));
}

__device__ __forceinline__ void mma_tf32(float c[4], uint32_t a0, uint32_t a1,
                                         uint32_t a2, uint32_t a3,
                                         uint32_t b0, uint32_t b1) {
    asm volatile(
        "mma.sync.aligned.m16n8k8.row.col.f32.tf32.tf32.f32 "
        "{%0,%1,%2,%3}, {%4,%5,%6,%7}, {%8,%9}, {%0,%1,%2,%3};"
        : "+f"(c[0]), "+f"(c[1]), "+f"(c[2]), "+f"(c[3])
        : "r"(a0), "r"(a1), "r"(a2), "r"(a3), "r"(b0), "r"(b1));
}

#define CP16(dst, src) \
    asm volatile("cp.async.cg.shared.global [%0], [%1], 16;" :: "r"(dst), "l"(src))
#define CP_COMMIT() asm volatile("cp.async.commit_group;")
#define CP_WAIT(n)  asm volatile("cp.async.wait_group %0;" :: "n"(n))

// ---------------- fp16 tensor-core GEMM, cp.async 4-stage pipeline -----------
// C[M,N] = A[M,K] @ Bt[N,K]^T (+bias,+relu). CTA 128x128, BK=32 halves, 256 thr,
// warp tile 64x32 (m16n8k16). Tiles [128][HROW] halves; HROW=40 -> 80B rows,
// fragment banks (20g+t)%32 = 32 distinct -> conflict-free, rows 16B-aligned.
// OUTH: 0 = fp32 C, 1 = fp16 C.
#define HROW 40
#define TILE_H (128 * HROW)           // halves per operand tile
#define ABYTES (TILE_H * 2)           // 10240 B
#define STG_BYTES (2 * ABYTES)        // 20480 B (A + B)
#define GSTAGES 4
#define GEMM_SMEM (GSTAGES * STG_BYTES)

__device__ __forceinline__ void load_tile_h(uint32_t sbase,
                                            const __half* __restrict__ gA, int lda,
                                            const __half* __restrict__ gB, int ldb,
                                            int tid) {
    #pragma unroll
    for (int i = 0; i < 2; i++) {
        int u = tid + i * 256;               // 0..511 : 128 rows x 4 x 16B
        int row = u >> 2, c = u & 3;
        CP16(sbase + row * 80 + c * 16, gA + (long long)row * lda + c * 8);
    }
    #pragma unroll
    for (int i = 0; i < 2; i++) {
        int u = tid + i * 256;
        int row = u >> 2, c = u & 3;
        CP16(sbase + ABYTES + row * 80 + c * 16, gB + (long long)row * ldb + c * 8);
    }
}

template <int ACT, int OUTH>
__global__ __launch_bounds__(256)
void hgemm_kernel(const __half* __restrict__ A, int lda, long long strideA,
                  const __half* __restrict__ Bt, int ldb,
                  void* __restrict__ Cv, int ldc, long long strideC,
                  int K, const float* __restrict__ bias) {
    A += (long long)blockIdx.z * strideA;

    extern __shared__ __half smh[];
    const int tid = threadIdx.x;
    const int lane = tid & 31;
    const int warp = tid >> 5;
    const int warpM = warp >> 2;
    const int warpN = warp & 3;
    const int tg = lane & 3;
    const int gid = lane >> 2;

    uint32_t sbase;
    asm("{ .reg .u64 t; cvta.to.shared.u64 t, %1; cvt.u32.u64 %0, t; }"
        : "=r"(sbase) : "l"(smh));

    float acc[4][4][4];
    #pragma unroll
    for (int i = 0; i < 4; i++)
        #pragma unroll
        for (int j = 0; j < 4; j++)
            #pragma unroll
            for (int q = 0; q < 4; q++) acc[i][j][q] = 0.0f;

    const __half* Ag = A + (long long)blockIdx.y * 128 * lda;
    const __half* Bg = Bt + (long long)blockIdx.x * 128 * ldb;
    const int ntile = K >> 5;

    // prologue: fill GSTAGES-1 stages
    #pragma unroll
    for (int p = 0; p < GSTAGES - 1; p++) {
        load_tile_h(sbase + p * STG_BYTES, Ag + p * 32, lda, Bg + p * 32, ldb, tid);
        CP_COMMIT();
    }

    for (int t = 0; t < ntile; t++) {
        CP_WAIT(GSTAGES - 2);
        __syncthreads();

        int f = t + GSTAGES - 1;
        if (f < ntile)
            load_tile_h(sbase + (f % GSTAGES) * STG_BYTES, Ag + f * 32, lda,
                        Bg + f * 32, ldb, tid);
        CP_COMMIT();

        const uint32_t Ab = sbase + (t % GSTAGES) * STG_BYTES;
        const uint32_t Bb = Ab + ABYTES;

        #pragma unroll
        for (int ks = 0; ks < 2; ks++) {
            const int kbB = ks * 32;          // byte offset of k-step (16 halves)
            uint32_t af[4][4], bf[4][2];
            #pragma unroll
            for (int mi = 0; mi < 4; mi++) {
                uint32_t r0 = Ab + (warpM * 64 + mi * 16 + gid) * 80 + kbB + tg * 4;
                asm volatile("ld.shared.b32 %0, [%1];" : "=r"(af[mi][0]) : "r"(r0));
                asm volatile("ld.shared.b32 %0, [%1];" : "=r"(af[mi][1]) : "r"(r0 + 8 * 80));
                asm volatile("ld.shared.b32 %0, [%1];" : "=r"(af[mi][2]) : "r"(r0 + 16));
                asm volatile("ld.shared.b32 %0, [%1];" : "=r"(af[mi][3]) : "r"(r0 + 8 * 80 + 16));
            }
            #pragma unroll
            for (int ni = 0; ni < 4; ni++) {
                uint32_t r0 = Bb + (warpN * 32 + ni * 8 + gid) * 80 + kbB + tg * 4;
                asm volatile("ld.shared.b32 %0, [%1];" : "=r"(bf[ni][0]) : "r"(r0));
                asm volatile("ld.shared.b32 %0, [%1];" : "=r"(bf[ni][1]) : "r"(r0 + 16));
            }
            #pragma unroll
            for (int mi = 0; mi < 4; mi++)
                #pragma unroll
                for (int ni = 0; ni < 4; ni++)
                    mma_f16(acc[mi][ni], af[mi][0], af[mi][1], af[mi][2], af[mi][3],
                            bf[ni][0], bf[ni][1]);
        }
        __syncthreads();
    }

    const int mbase = blockIdx.y * 128 + warpM * 64;
    const int nbase = blockIdx.x * 128 + warpN * 32;
    #pragma unroll
    for (int ni = 0; ni < 4; ni++) {
        int c0 = nbase + ni * 8 + tg * 2;
        float bv0 = 0.0f, bv1 = 0.0f;
        if (ACT > 0) { bv0 = bias[c0]; bv1 = bias[c0 + 1]; }
        #pragma unroll
        for (int mi = 0; mi < 4; mi++) {
            int r0 = mbase + mi * 16 + gid;
            float v00 = acc[mi][ni][0] + bv0;
            float v01 = acc[mi][ni][1] + bv1;
            float v10 = acc[mi][ni][2] + bv0;
            float v11 = acc[mi][ni][3] + bv1;
            if (ACT == 2) {
                v00 = fmaxf(v00, 0.0f); v01 = fmaxf(v01, 0.0f);
                v10 = fmaxf(v10, 0.0f); v11 = fmaxf(v11, 0.0f);
            }
            if (OUTH) {
                __half* C = (__half*)Cv + (long long)blockIdx.z * strideC;
                __half2 h0 = __floats2half2_rn(v00, v01);
                __half2 h1 = __floats2half2_rn(v10, v11);
                *(__half2*)(C + (long long)r0 * ldc + c0) = h0;
                *(__half2*)(C + (long long)(r0 + 8) * ldc + c0) = h1;
            } else {
                float* C = (float*)Cv + (long long)blockIdx.z * strideC;
                *(float2*)(C + (long long)r0 * ldc + c0) = make_float2(v00, v01);
                *(float2*)(C + (long long)(r0 + 8) * ldc + c0) = make_float2(v10, v11);
            }
        }
    }
}

// ---------------- tensor-core flash attention (causal, fp16 out) -------------
#define KSP 68
#define VSP 72

__global__ __launch_bounds__(128)
void flash_attn_tc_kernel(const float* __restrict__ qkv, __half* __restrict__ out) {
    __shared__ uint32_t Ks[64][KSP];
    __shared__ uint32_t Vs[64][VSP];

    const int qb = (gridDim.x - 1) - blockIdx.x;
    const int bh = blockIdx.y;
    const int b = bh >> 3, h = bh & 7;
    const int tid = threadIdx.x;
    const int lane = tid & 31;
    const int warp = tid >> 5;
    const int g = lane >> 2;
    const int t = lane & 3;

    const long long rstride = 3 * CDIM;

    const float* qptr = qkv + ((long long)(b * T_SEQ + qb * 64 + warp * 16)) * rstride + h * HD;
    uint32_t qf[8][4];
    #pragma unroll
    for (int ks = 0; ks < 8; ks++) {
        qf[ks][0] = __float_as_uint(0.125f * __ldg(qptr + (long long)g * rstride + ks * 8 + t));
        qf[ks][1] = __float_as_uint(0.125f * __ldg(qptr + (long long)(g + 8) * rstride + ks * 8 + t));
        qf[ks][2] = __float_as_uint(0.125f * __ldg(qptr + (long long)g * rstride + ks * 8 + t + 4));
        qf[ks][3] = __float_as_uint(0.125f * __ldg(qptr + (long long)(g + 8) * rstride + ks * 8 + t + 4));
    }

    float o[8][4];
    #pragma unroll
    for (int ni = 0; ni < 8; ni++)
        #pragma unroll
        for (int q = 0; q < 4; q++) o[ni][q] = 0.0f;
    float m0 = -1e30f, m1 = -1e30f, l0 = 0.0f, l1 = 0.0f;

    const int row0 = qb * 64 + warp * 16 + g;
    const int row1 = row0 + 8;

    for (int kb = 0; kb <= qb; kb++) {
        const float* kbase = qkv + ((long long)(b * T_SEQ + kb * 64)) * rstride + CDIM + h * HD;
        const float* vbase = kbase + CDIM;
        #pragma unroll
        for (int i = 0; i < 8; i++) {
            int idx = tid + i * 128;
            int r = idx >> 4, c4 = idx & 15;
            float4 kv = *(const float4*)(kbase + (long long)r * rstride + c4 * 4);
            Ks[r][c4 * 4 + 0] = __float_as_uint(kv.x);
            Ks[r][c4 * 4 + 1] = __float_as_uint(kv.y);
            Ks[r][c4 * 4 + 2] = __float_as_uint(kv.z);
            Ks[r][c4 * 4 + 3] = __float_as_uint(kv.w);
            float4 vv = *(const float4*)(vbase + (long long)r * rstride + c4 * 4);
            int pr = (r & 56) | ((r & 1) << 2) | ((r >> 1) & 3);
            Vs[pr][c4 * 4 + 0] = __float_as_uint(vv.x);
            Vs[pr][c4 * 4 + 1] = __float_as_uint(vv.y);
            Vs[pr][c4 * 4 + 2] = __float_as_uint(vv.z);
            Vs[pr][c4 * 4 + 3] = __float_as_uint(vv.w);
        }
        __syncthreads();

        float s[8][4];
        #pragma unroll
        for (int ni = 0; ni < 8; ni++) {
            s[ni][0] = s[ni][1] = s[ni][2] = s[ni][3] = 0.0f;
            #pragma unroll
            for (int ks = 0; ks < 8; ks++) {
                uint32_t b0 = Ks[ni * 8 + g][ks * 8 + t];
                uint32_t b1 = Ks[ni * 8 + g][ks * 8 + t + 4];
                mma_tf32(s[ni], qf[ks][0], qf[ks][1], qf[ks][2], qf[ks][3], b0, b1);
            }
        }

        if (kb == qb) {
            #pragma unroll
            for (int ni = 0; ni < 8; ni++) {
                int col = kb * 64 + ni * 8 + 2 * t;
                if (col > row0)     s[ni][0] = -1e30f;
                if (col + 1 > row0) s[ni][1] = -1e30f;
                if (col > row1)     s[ni][2] = -1e30f;
                if (col + 1 > row1) s[ni][3] = -1e30f;
            }
        }

        float mt0 = -1e30f, mt1 = -1e30f;
        #pragma unroll
        for (int ni = 0; ni < 8; ni++) {
            mt0 = fmaxf(mt0, fmaxf(s[ni][0], s[ni][1]));
            mt1 = fmaxf(mt1, fmaxf(s[ni][2], s[ni][3]));
        }
        mt0 = fmaxf(mt0, __shfl_xor_sync(0xffffffffu, mt0, 1));
        mt0 = fmaxf(mt0, __shfl_xor_sync(0xffffffffu, mt0, 2));
        mt1 = fmaxf(mt1, __shfl_xor_sync(0xffffffffu, mt1, 1));
        mt1 = fmaxf(mt1, __shfl_xor_sync(0xffffffffu, mt1, 2));

        float mn0 = fmaxf(m0, mt0), mn1 = fmaxf(m1, mt1);
        float corr0 = __expf(m0 - mn0), corr1 = __expf(m1 - mn1);
        m0 = mn0; m1 = mn1;

        float ps0 = 0.0f, ps1 = 0.0f;
        uint32_t pf[8][4];
        #pragma unroll
        for (int ni = 0; ni < 8; ni++) {
            float p0 = __expf(s[ni][0] - mn0);
            float p1 = __expf(s[ni][1] - mn0);
            float p2 = __expf(s[ni][2] - mn1);
            float p3 = __expf(s[ni][3] - mn1);
            ps0 += p0 + p1;
            ps1 += p2 + p3;
            pf[ni][0] = __float_as_uint(p0);
            pf[ni][1] = __float_as_uint(p2);
            pf[ni][2] = __float_as_uint(p1);
            pf[ni][3] = __float_as_uint(p3);
        }
        ps0 += __shfl_xor_sync(0xffffffffu, ps0, 1);
        ps0 += __shfl_xor_sync(0xffffffffu, ps0, 2);
        ps1 += __shfl_xor_sync(0xffffffffu, ps1, 1);
        ps1 += __shfl_xor_sync(0xffffffffu, ps1, 2);
        l0 = l0 * corr0 + ps0;
        l1 = l1 * corr1 + ps1;

        #pragma unroll
        for (int ni = 0; ni < 8; ni++) {
            o[ni][0] *= corr0;
            o[ni][1] *= corr0;
            o[ni][2] *= corr1;
            o[ni][3] *= corr1;
        }

        #pragma unroll
        for (int ni = 0; ni < 8; ni++) {
            #pragma unroll
            for (int ks = 0; ks < 8; ks++) {
                uint32_t b0 = Vs[ks * 8 + t][ni * 8 + g];
                uint32_t b1 = Vs[ks * 8 + t + 4][ni * 8 + g];
                mma_tf32(o[ni], pf[ks][0], pf[ks][1], pf[ks][2], pf[ks][3], b0, b1);
            }
        }
        __syncthreads();
    }

    float inv0 = 1.0f / l0, inv1 = 1.0f / l1;
    __half* obase = out + ((long long)(b * T_SEQ)) * CDIM + h * HD;
    #pragma unroll
    for (int ni = 0; ni < 8; ni++) {
        int col = ni * 8 + 2 * t;
        *(__half2*)(obase + (long long)row0 * CDIM + col) =
            __floats2half2_rn(o[ni][0] * inv0, o[ni][1] * inv0);
        *(__half2*)(obase + (long long)row1 * CDIM + col) =
            __floats2half2_rn(o[ni][2] * inv1, o[ni][3] * inv1);
    }
}

// ---------------- launch -----------------------------------------------------
extern "C" void kernel_launch(void* const* d_in, const int* in_sizes, int n_in,
                              void* d_out, int out_size) {
    const float* x      = (const float*)d_in[0];
    const float* conv_w = (const float*)d_in[1];
    const float* conv_b = (const float*)d_in[2];
    const float* g1     = (const float*)d_in[3];
    const float* b1     = (const float*)d_in[4];
    const float* qkv_w  = (const float*)d_in[5];
    const float* qkv_b  = (const float*)d_in[6];
    const float* proj_w = (const float*)d_in[7];
    const float* proj_b = (const float*)d_in[8];
    const float* g2     = (const float*)d_in[9];
    const float* b2     = (const float*)d_in[10];
    const float* ffn_w1 = (const float*)d_in[11];
    const float* ffn_b1 = (const float*)d_in[12];
    const float* ffn_w2 = (const float*)d_in[13];
    const float* ffn_b2 = (const float*)d_in[14];
    const float* g3     = (const float*)d_in[15];
    const float* b3     = (const float*)d_in[16];
    float* out = (float*)d_out;

    __half *xpad, *wcT, *qkvT, *projT, *ffn1T, *ffn2T, *x1h, *x2h, *attnh, *ffnhh;
    float *conv, *x1, *qkvb, *proj, *x2, *ffn2;
    cudaGetSymbolAddress((void**)&xpad,  g_xpad);
    cudaGetSymbolAddress((void**)&wcT,   g_wcT);
    cudaGetSymbolAddress((void**)&qkvT,  g_qkvT);
    cudaGetSymbolAddress((void**)&projT, g_projT);
    cudaGetSymbolAddress((void**)&ffn1T, g_ffn1T);
    cudaGetSymbolAddress((void**)&ffn2T, g_ffn2T);
    cudaGetSymbolAddress((void**)&x1h,   g_x1h);
    cudaGetSymbolAddress((void**)&x2h,   g_x2h);
    cudaGetSymbolAddress((void**)&attnh, g_attnh);
    cudaGetSymbolAddress((void**)&ffnhh, g_ffnhh);
    cudaGetSymbolAddress((void**)&conv,  g_conv);
    cudaGetSymbolAddress((void**)&x1,    g_x1);
    cudaGetSymbolAddress((void**)&qkvb,  g_qkv);
    cudaGetSymbolAddress((void**)&proj,  g_proj);
    cudaGetSymbolAddress((void**)&x2,    g_x2);
    cudaGetSymbolAddress((void**)&ffn2,  g_ffn2);

    cudaFuncSetAttribute(hgemm_kernel<1, 0>,
                         cudaFuncAttributeMaxDynamicSharedMemorySize, GEMM_SMEM);
    cudaFuncSetAttribute(hgemm_kernel<2, 1>,
                         cudaFuncAttributeMaxDynamicSharedMemorySize, GEMM_SMEM);

    // prep: padding (fp16) + weight transposes (fp16)
    {
        int total = BDIM * (T_SEQ + 2) * CDIM;
        pad_kernel<<<(total + 255) / 256, 256>>>(x, xpad);
    }
    wconvT_kernel<<<(CDIM * 3 * CDIM + 255) / 256, 256>>>(conv_w, wcT);
    transpose_kernel<<<dim3(3 * CDIM / 32, CDIM / 32), dim3(32, 8)>>>(qkv_w, qkvT, CDIM, 3 * CDIM);
    transpose_kernel<<<dim3(CDIM / 32, CDIM / 32), dim3(32, 8)>>>(proj_w, projT, CDIM, CDIM);
    transpose_kernel<<<dim3(2 * CDIM / 32, CDIM / 32), dim3(32, 8)>>>(ffn_w1, ffn1T, CDIM, 2 * CDIM);
    transpose_kernel<<<dim3(CDIM / 32, 2 * CDIM / 32), dim3(32, 8)>>>(ffn_w2, ffn2T, 2 * CDIM, CDIM);

    // conv as GEMM: per batch M=2048, N=512, K=1536 (overlapping A rows)
    hgemm_kernel<1, 0><<<dim3(4, 16, 2), 256, GEMM_SMEM>>>(
        xpad, CDIM, (long long)(T_SEQ + 2) * CDIM,
        wcT, 3 * CDIM,
        conv, CDIM, (long long)T_SEQ * CDIM,
        3 * CDIM, conv_b);

    add_ln_kernel<<<BT, 128>>>(x, conv, g1, b1, x1, x1h);

    // qkv: M=4096, N=1536, K=512 (fp32 out for attention)
    hgemm_kernel<1, 0><<<dim3(12, 32, 1), 256, GEMM_SMEM>>>(
        x1h, CDIM, 0, qkvT, CDIM, qkvb, 3 * CDIM, 0, CDIM, qkv_b);

    flash_attn_tc_kernel<<<dim3(T_SEQ / 64, BDIM * HNUM), 128>>>(qkvb, attnh);

    // proj: M=4096, N=512, K=512
    hgemm_kernel<1, 0><<<dim3(4, 32, 1), 256, GEMM_SMEM>>>(
        attnh, CDIM, 0, projT, CDIM, proj, CDIM, 0, CDIM, proj_b);

    add_ln_kernel<<<BT, 128>>>(x1, proj, g2, b2, x2, x2h);

    // ffn1: M=4096, N=1024, K=512, relu, fp16 out
    hgemm_kernel<2, 1><<<dim3(8, 32, 1), 256, GEMM_SMEM>>>(
        x2h, CDIM, 0, ffn1T, CDIM, ffnhh, 2 * CDIM, 0, CDIM, ffn_b1);

    // ffn2: M=4096, N=512, K=1024
    hgemm_kernel<1, 0><<<dim3(4, 32, 1), 256, GEMM_SMEM>>>(
        ffnhh, 2 * CDIM, 0, ffn2T, 2 * CDIM, ffn2, CDIM, 0, 2 * CDIM, ffn_b2);

    add_ln_kernel<<<BT, 128>>>(x2, ffn2, g3, b3, out, (__half*)nullptr);
}

// round 7
// speedup vs baseline: 4.6441x; 1.0767x over previous
#include <cuda_runtime.h>
#include <cuda_fp16.h>
#include <cstdint>

// Problem constants
#define T_SEQ 2048
#define CDIM  512
#define BDIM  2
#define HNUM  8
#define HD    64
#define BT    (BDIM * T_SEQ)

// ---------------- scratch (device globals; no allocation allowed) ----------
__device__ __half g_xpad [BDIM * (T_SEQ + 2) * CDIM];
__device__ __half g_wcT  [CDIM * 3 * CDIM];     // [o][k*512+i]
__device__ __half g_qkvT [3 * CDIM * CDIM];     // [1536][512]
__device__ __half g_projT[CDIM * CDIM];         // [512][512]
__device__ __half g_ffn1T[2 * CDIM * CDIM];     // [1024][512]
__device__ __half g_ffn2T[CDIM * 2 * CDIM];     // [512][1024]
__device__ __half g_x1h  [BT * CDIM];
__device__ __half g_x2h  [BT * CDIM];
__device__ __half g_qkvh [BT * 3 * CDIM];
__device__ __half g_attnh[BT * CDIM];
__device__ __half g_ffnhh[BT * 2 * CDIM];
__device__ float  g_conv [BT * CDIM];
__device__ float  g_x1   [BT * CDIM];
__device__ float  g_proj [BT * CDIM];
__device__ float  g_x2   [BT * CDIM];
__device__ float  g_ffn2 [BT * CDIM];

// ---------------- small prep kernels ---------------------------------------
__global__ void pad_kernel(const float* __restrict__ x, __half* __restrict__ xpad) {
    int idx = blockIdx.x * blockDim.x + threadIdx.x;
    const int total = BDIM * (T_SEQ + 2) * CDIM;
    if (idx >= total) return;
    int c = idx % CDIM;
    int t = (idx / CDIM) % (T_SEQ + 2);
    int b = idx / (CDIM * (T_SEQ + 2));
    float v = (t < 2) ? 0.0f : x[((long long)b * T_SEQ + (t - 2)) * CDIM + c];
    xpad[idx] = __float2half_rn(v);
}

// conv_w OIH [o][i][k] -> wcT[o][k*512+i]  (B^T for the conv GEMM)
__global__ void wconvT_kernel(const float* __restrict__ w, __half* __restrict__ outp) {
    int idx = blockIdx.x * blockDim.x + threadIdx.x;
    const int total = CDIM * 3 * CDIM;
    if (idx >= total) return;
    int o = idx / (3 * CDIM);
    int r = idx % (3 * CDIM);
    int k = r / CDIM;
    int i = r % CDIM;
    outp[idx] = __float2half_rn(w[((long long)o * CDIM + i) * 3 + k]);
}

// [K][N] fp32 -> [N][K] fp16 tiled transpose. blockDim (32,8), grid (N/32, K/32).
__global__ void transpose_kernel(const float* __restrict__ in, __half* __restrict__ outp,
                                 int K, int N) {
    __shared__ float tile[32][33];
    int bx = blockIdx.x * 32, by = blockIdx.y * 32;
    #pragma unroll
    for (int j = 0; j < 32; j += 8)
        tile[threadIdx.y + j][threadIdx.x] =
            in[(long long)(by + threadIdx.y + j) * N + bx + threadIdx.x];
    __syncthreads();
    #pragma unroll
    for (int j = 0; j < 32; j += 8)
        outp[(long long)(bx + threadIdx.y + j) * K + by + threadIdx.x] =
            __float2half_rn(tile[threadIdx.x][threadIdx.y + j]);
}

// ---------------- fused residual add + LayerNorm (dual fp32/fp16 out) -------
__global__ void add_ln_kernel(const float* __restrict__ a, const float* __restrict__ r,
                              const float* __restrict__ g, const float* __restrict__ be,
                              float* __restrict__ out, __half* __restrict__ outh) {
    __shared__ float sh[4];
    int row = blockIdx.x;
    int tid = threadIdx.x;
    const float4 va = ((const float4*)(a + (long long)row * CDIM))[tid];
    const float4 vr = ((const float4*)(r + (long long)row * CDIM))[tid];
    float x0 = va.x + vr.x, x1 = va.y + vr.y, x2 = va.z + vr.z, x3 = va.w + vr.w;

    float s = x0 + x1 + x2 + x3;
    #pragma unroll
    for (int o = 16; o; o >>= 1) s += __shfl_xor_sync(0xffffffffu, s, o);
    if ((tid & 31) == 0) sh[tid >> 5] = s;
    __syncthreads();
    float mean = (sh[0] + sh[1] + sh[2] + sh[3]) * (1.0f / CDIM);
    __syncthreads();

    float d0 = x0 - mean, d1 = x1 - mean, d2 = x2 - mean, d3 = x3 - mean;
    float ss = d0 * d0 + d1 * d1 + d2 * d2 + d3 * d3;
    #pragma unroll
    for (int o = 16; o; o >>= 1) ss += __shfl_xor_sync(0xffffffffu, ss, o);
    if ((tid & 31) == 0) sh[tid >> 5] = ss;
    __syncthreads();
    float var = (sh[0] + sh[1] + sh[2] + sh[3]) * (1.0f / CDIM);
    float rs = rsqrtf(var + 1e-5f);

    float4 vg = ((const float4*)g)[tid];
    float4 vb = ((const float4*)be)[tid];
    float4 o4;
    o4.x = d0 * rs * vg.x + vb.x;
    o4.y = d1 * rs * vg.y + vb.y;
    o4.z = d2 * rs * vg.z + vb.z;
    o4.w = d3 * rs * vg.w + vb.w;
    ((float4*)(out + (long long)row * CDIM))[tid] = o4;
    if (outh) {
        __half2 h0 = __floats2half2_rn(o4.x, o4.y);
        __half2 h1 = __floats2half2_rn(o4.z, o4.w);
        *(uint2*)(outh + (long long)row * CDIM + tid * 4) =
            make_uint2(*(uint32_t*)&h0, *(uint32_t*)&h1);
    }
}

// ---------------- mma helper --------------------------------------------------
__device__ __forceinline__ void mma_f16(float c[4], uint32_t a0, uint32_t a1,
                                        uint32_t a2, uint32_t a3,
                                        uint32_t b0, uint32_t b1) {
    asm volatile(
        "mma.sync.aligned.m16n8k16.row.col.f32.f16.f16.f32 "
        "{%0,%1,%2,%3}, {%4,%5,%6,%7}, {%8,%9}, {%0,%1,%2,%3};"
        : "+f"(c[0]), "+f"(c[1]), "+f"(c[2]), "+f"(c[3])
        : "r"(a0), "r"(a1), "r"(a2), "r"(a3), "r"(b0), "r"(b1));
}

#define CP16(dst, src) \
    asm volatile("cp.async.cg.shared.global [%0], [%1], 16;" :: "r"(dst), "l"(src))
#define CP_COMMIT() asm volatile("cp.async.commit_group;")
#define CP_WAIT(n)  asm volatile("cp.async.wait_group %0;" :: "n"(n))

// ---------------- fp16 tensor-core GEMM, cp.async 3-stage, 2 CTAs/SM ---------
#define HROW 40
#define TILE_H (128 * HROW)
#define ABYTES (TILE_H * 2)           // 10240 B
#define STG_BYTES (2 * ABYTES)        // 20480 B
#define GSTAGES 3
#define GEMM_SMEM (GSTAGES * STG_BYTES)   // 61440 B

__device__ __forceinline__ void load_tile_h(uint32_t sbase,
                                            const __half* __restrict__ gA, int lda,
                                            const __half* __restrict__ gB, int ldb,
                                            int tid) {
    #pragma unroll
    for (int i = 0; i < 2; i++) {
        int u = tid + i * 256;
        int row = u >> 2, c = u & 3;
        CP16(sbase + row * 80 + c * 16, gA + (long long)row * lda + c * 8);
    }
    #pragma unroll
    for (int i = 0; i < 2; i++) {
        int u = tid + i * 256;
        int row = u >> 2, c = u & 3;
        CP16(sbase + ABYTES + row * 80 + c * 16, gB + (long long)row * ldb + c * 8);
    }
}

template <int ACT, int OUTH>
__global__ __launch_bounds__(256, 2)
void hgemm_kernel(const __half* __restrict__ A, int lda, long long strideA,
                  const __half* __restrict__ Bt, int ldb,
                  void* __restrict__ Cv, int ldc, long long strideC,
                  int K, const float* __restrict__ bias) {
    A += (long long)blockIdx.z * strideA;

    extern __shared__ __half smh[];
    const int tid = threadIdx.x;
    const int lane = tid & 31;
    const int warp = tid >> 5;
    const int warpM = warp >> 2;
    const int warpN = warp & 3;
    const int tg = lane & 3;
    const int gid = lane >> 2;

    uint32_t sbase;
    asm("{ .reg .u64 t; cvta.to.shared.u64 t, %1; cvt.u32.u64 %0, t; }"
        : "=r"(sbase) : "l"(smh));

    float acc[4][4][4];
    #pragma unroll
    for (int i = 0; i < 4; i++)
        #pragma unroll
        for (int j = 0; j < 4; j++)
            #pragma unroll
            for (int q = 0; q < 4; q++) acc[i][j][q] = 0.0f;

    const __half* Ag = A + (long long)blockIdx.y * 128 * lda;
    const __half* Bg = Bt + (long long)blockIdx.x * 128 * ldb;
    const int ntile = K >> 5;

    #pragma unroll
    for (int p = 0; p < GSTAGES - 1; p++) {
        load_tile_h(sbase + p * STG_BYTES, Ag + p * 32, lda, Bg + p * 32, ldb, tid);
        CP_COMMIT();
    }

    for (int t = 0; t < ntile; t++) {
        CP_WAIT(GSTAGES - 2);
        __syncthreads();

        int f = t + GSTAGES - 1;
        if (f < ntile)
            load_tile_h(sbase + (f % GSTAGES) * STG_BYTES, Ag + f * 32, lda,
                        Bg + f * 32, ldb, tid);
        CP_COMMIT();

        const uint32_t Ab = sbase + (t % GSTAGES) * STG_BYTES;
        const uint32_t Bb = Ab + ABYTES;

        #pragma unroll
        for (int ks = 0; ks < 2; ks++) {
            const int kbB = ks * 32;
            uint32_t af[4][4], bf[4][2];
            #pragma unroll
            for (int mi = 0; mi < 4; mi++) {
                uint32_t r0 = Ab + (warpM * 64 + mi * 16 + gid) * 80 + kbB + tg * 4;
                asm volatile("ld.shared.b32 %0, [%1];" : "=r"(af[mi][0]) : "r"(r0));
                asm volatile("ld.shared.b32 %0, [%1];" : "=r"(af[mi][1]) : "r"(r0 + 8 * 80));
                asm volatile("ld.shared.b32 %0, [%1];" : "=r"(af[mi][2]) : "r"(r0 + 16));
                asm volatile("ld.shared.b32 %0, [%1];" : "=r"(af[mi][3]) : "r"(r0 + 8 * 80 + 16));
            }
            #pragma unroll
            for (int ni = 0; ni < 4; ni++) {
                uint32_t r0 = Bb + (warpN * 32 + ni * 8 + gid) * 80 + kbB + tg * 4;
                asm volatile("ld.shared.b32 %0, [%1];" : "=r"(bf[ni][0]) : "r"(r0));
                asm volatile("ld.shared.b32 %0, [%1];" : "=r"(bf[ni][1]) : "r"(r0 + 16));
            }
            #pragma unroll
            for (int mi = 0; mi < 4; mi++)
                #pragma unroll
                for (int ni = 0; ni < 4; ni++)
                    mma_f16(acc[mi][ni], af[mi][0], af[mi][1], af[mi][2], af[mi][3],
                            bf[ni][0], bf[ni][1]);
        }
        __syncthreads();
    }

    const int mbase = blockIdx.y * 128 + warpM * 64;
    const int nbase = blockIdx.x * 128 + warpN * 32;
    #pragma unroll
    for (int ni = 0; ni < 4; ni++) {
        int c0 = nbase + ni * 8 + tg * 2;
        float bv0 = 0.0f, bv1 = 0.0f;
        if (ACT > 0) { bv0 = bias[c0]; bv1 = bias[c0 + 1]; }
        #pragma unroll
        for (int mi = 0; mi < 4; mi++) {
            int r0 = mbase + mi * 16 + gid;
            float v00 = acc[mi][ni][0] + bv0;
            float v01 = acc[mi][ni][1] + bv1;
            float v10 = acc[mi][ni][2] + bv0;
            float v11 = acc[mi][ni][3] + bv1;
            if (ACT == 2) {
                v00 = fmaxf(v00, 0.0f); v01 = fmaxf(v01, 0.0f);
                v10 = fmaxf(v10, 0.0f); v11 = fmaxf(v11, 0.0f);
            }
            if (OUTH) {
                __half* C = (__half*)Cv + (long long)blockIdx.z * strideC;
                *(__half2*)(C + (long long)r0 * ldc + c0) = __floats2half2_rn(v00, v01);
                *(__half2*)(C + (long long)(r0 + 8) * ldc + c0) = __floats2half2_rn(v10, v11);
            } else {
                float* C = (float*)Cv + (long long)blockIdx.z * strideC;
                *(float2*)(C + (long long)r0 * ldc + c0) = make_float2(v00, v01);
                *(float2*)(C + (long long)(r0 + 8) * ldc + c0) = make_float2(v10, v11);
            }
        }
    }
}

// ---------------- fp16 tensor-core flash attention (causal) ------------------
// grid (T/64, B*H), 128 thr = 4 warps x 16 q-rows. m16n8k16 for QK^T and PV.
// K smem [key][dim] stride 72 halves (read banks (4g+t+8ks)%32 distinct).
// V smem transposed [dim][key] stride 76 halves (read banks (6g+t+8j+16ni)%32
// distinct; stores 2-way). P C-frag packs directly into PV A-frag half2s.
#define KS_STRIDE 72
#define VT_STRIDE 76

__global__ __launch_bounds__(128)
void flash_attn_h_kernel(const __half* __restrict__ qkv, __half* __restrict__ out) {
    __shared__ __half Ks[64 * KS_STRIDE];
    __shared__ __half Vt[64 * VT_STRIDE];

    const int qb = (gridDim.x - 1) - blockIdx.x;   // heavy blocks first
    const int bh = blockIdx.y;
    const int b = bh >> 3, h = bh & 7;
    const int tid = threadIdx.x;
    const int lane = tid & 31;
    const int warp = tid >> 5;
    const int g = lane >> 2;
    const int t = lane & 3;
    const long long rstride = 3 * CDIM;

    // Q fragments (fp16, unscaled; scores scaled post-mma)
    const __half* q0 = qkv + ((long long)(b * T_SEQ + qb * 64 + warp * 16)) * rstride + h * HD;
    uint32_t qf[4][4];
    #pragma unroll
    for (int ks = 0; ks < 4; ks++) {
        qf[ks][0] = *(const uint32_t*)(q0 + (long long)g * rstride + ks * 16 + 2 * t);
        qf[ks][1] = *(const uint32_t*)(q0 + (long long)(g + 8) * rstride + ks * 16 + 2 * t);
        qf[ks][2] = *(const uint32_t*)(q0 + (long long)g * rstride + ks * 16 + 8 + 2 * t);
        qf[ks][3] = *(const uint32_t*)(q0 + (long long)(g + 8) * rstride + ks * 16 + 8 + 2 * t);
    }

    float o[8][4];
    #pragma unroll
    for (int ni = 0; ni < 8; ni++)
        #pragma unroll
        for (int q = 0; q < 4; q++) o[ni][q] = 0.0f;
    float m0 = -1e30f, m1 = -1e30f, l0 = 0.0f, l1 = 0.0f;

    const int row0 = qb * 64 + warp * 16 + g;
    const int row1 = row0 + 8;

    for (int kb = 0; kb <= qb; kb++) {
        const __half* kbase = qkv + ((long long)(b * T_SEQ + kb * 64)) * rstride + CDIM + h * HD;
        const __half* vbase = kbase + CDIM;

        // K copy: 64 rows x 64 halves (16B chunks)
        #pragma unroll
        for (int i = 0; i < 4; i++) {
            int u = tid + i * 128;
            int r = u >> 3, c = u & 7;
            *(uint4*)&Ks[r * KS_STRIDE + c * 8] =
                *(const uint4*)(kbase + (long long)r * rstride + c * 8);
        }
        // V transpose: key-pairs -> half2 along keys
        #pragma unroll
        for (int i = 0; i < 2; i++) {
            int u = tid + i * 128;
            int kp = u >> 3, d8 = u & 7;
            uint4 va = *(const uint4*)(vbase + (long long)(2 * kp) * rstride + d8 * 8);
            uint4 vb = *(const uint4*)(vbase + (long long)(2 * kp + 1) * rstride + d8 * 8);
            const __half* ah = (const __half*)&va;
            const __half* bhp = (const __half*)&vb;
            #pragma unroll
            for (int j = 0; j < 8; j++)
                *(__half2*)&Vt[(d8 * 8 + j) * VT_STRIDE + 2 * kp] =
                    __halves2half2(ah[j], bhp[j]);
        }
        __syncthreads();

        // S = Q @ K^T : 8 key-groups x 4 k16-steps
        float s[8][4];
        #pragma unroll
        for (int ni = 0; ni < 8; ni++) {
            s[ni][0] = s[ni][1] = s[ni][2] = s[ni][3] = 0.0f;
            const __half* kr = &Ks[(ni * 8 + g) * KS_STRIDE];
            #pragma unroll
            for (int ks = 0; ks < 4; ks++) {
                uint32_t b0 = *(const uint32_t*)(kr + ks * 16 + 2 * t);
                uint32_t b1 = *(const uint32_t*)(kr + ks * 16 + 8 + 2 * t);
                mma_f16(s[ni], qf[ks][0], qf[ks][1], qf[ks][2], qf[ks][3], b0, b1);
            }
            s[ni][0] *= 0.125f; s[ni][1] *= 0.125f;
            s[ni][2] *= 0.125f; s[ni][3] *= 0.125f;
        }

        // causal mask (diagonal tile only)
        if (kb == qb) {
            #pragma unroll
            for (int ni = 0; ni < 8; ni++) {
                int col = kb * 64 + ni * 8 + 2 * t;
                if (col > row0)     s[ni][0] = -1e30f;
                if (col + 1 > row0) s[ni][1] = -1e30f;
                if (col > row1)     s[ni][2] = -1e30f;
                if (col + 1 > row1) s[ni][3] = -1e30f;
            }
        }

        // online softmax
        float mt0 = -1e30f, mt1 = -1e30f;
        #pragma unroll
        for (int ni = 0; ni < 8; ni++) {
            mt0 = fmaxf(mt0, fmaxf(s[ni][0], s[ni][1]));
            mt1 = fmaxf(mt1, fmaxf(s[ni][2], s[ni][3]));
        }
        mt0 = fmaxf(mt0, __shfl_xor_sync(0xffffffffu, mt0, 1));
        mt0 = fmaxf(mt0, __shfl_xor_sync(0xffffffffu, mt0, 2));
        mt1 = fmaxf(mt1, __shfl_xor_sync(0xffffffffu, mt1, 1));
        mt1 = fmaxf(mt1, __shfl_xor_sync(0xffffffffu, mt1, 2));

        float mn0 = fmaxf(m0, mt0), mn1 = fmaxf(m1, mt1);
        float corr0 = __expf(m0 - mn0), corr1 = __expf(m1 - mn1);
        m0 = mn0; m1 = mn1;

        float ps0 = 0.0f, ps1 = 0.0f;
        float p[8][4];
        #pragma unroll
        for (int ni = 0; ni < 8; ni++) {
            p[ni][0] = __expf(s[ni][0] - mn0);
            p[ni][1] = __expf(s[ni][1] - mn0);
            p[ni][2] = __expf(s[ni][2] - mn1);
            p[ni][3] = __expf(s[ni][3] - mn1);
            ps0 += p[ni][0] + p[ni][1];
            ps1 += p[ni][2] + p[ni][3];
        }
        ps0 += __shfl_xor_sync(0xffffffffu, ps0, 1);
        ps0 += __shfl_xor_sync(0xffffffffu, ps0, 2);
        ps1 += __shfl_xor_sync(0xffffffffu, ps1, 1);
        ps1 += __shfl_xor_sync(0xffffffffu, ps1, 2);
        l0 = l0 * corr0 + ps0;
        l1 = l1 * corr1 + ps1;

        // P C-frag -> PV A-frag (direct half2 packing, no permutation)
        uint32_t pf[4][4];
        #pragma unroll
        for (int j = 0; j < 4; j++) {
            __half2 h0 = __floats2half2_rn(p[2 * j][0],     p[2 * j][1]);
            __half2 h1 = __floats2half2_rn(p[2 * j][2],     p[2 * j][3]);
            __half2 h2 = __floats2half2_rn(p[2 * j + 1][0], p[2 * j + 1][1]);
            __half2 h3 = __floats2half2_rn(p[2 * j + 1][2], p[2 * j + 1][3]);
            pf[j][0] = *(uint32_t*)&h0;
            pf[j][1] = *(uint32_t*)&h1;
            pf[j][2] = *(uint32_t*)&h2;
            pf[j][3] = *(uint32_t*)&h3;
        }

        #pragma unroll
        for (int ni = 0; ni < 8; ni++) {
            o[ni][0] *= corr0;
            o[ni][1] *= corr0;
            o[ni][2] *= corr1;
            o[ni][3] *= corr1;
        }

        // O += P @ V : 8 dim-groups x 4 k16-steps (keys)
        #pragma unroll
        for (int ni = 0; ni < 8; ni++) {
            const __half* vr = &Vt[(ni * 8 + g) * VT_STRIDE];
            #pragma unroll
            for (int j = 0; j < 4; j++) {
                uint32_t b0 = *(const uint32_t*)(vr + j * 16 + 2 * t);
                uint32_t b1 = *(const uint32_t*)(vr + j * 16 + 8 + 2 * t);
                mma_f16(o[ni], pf[j][0], pf[j][1], pf[j][2], pf[j][3], b0, b1);
            }
        }
        __syncthreads();
    }

    float inv0 = 1.0f / l0, inv1 = 1.0f / l1;
    __half* obase = out + ((long long)(b * T_SEQ)) * CDIM + h * HD;
    #pragma unroll
    for (int ni = 0; ni < 8; ni++) {
        int col = ni * 8 + 2 * t;
        *(__half2*)(obase + (long long)row0 * CDIM + col) =
            __floats2half2_rn(o[ni][0] * inv0, o[ni][1] * inv0);
        *(__half2*)(obase + (long long)row1 * CDIM + col) =
            __floats2half2_rn(o[ni][2] * inv1, o[ni][3] * inv1);
    }
}

// ---------------- launch -----------------------------------------------------
extern "C" void kernel_launch(void* const* d_in, const int* in_sizes, int n_in,
                              void* d_out, int out_size) {
    const float* x      = (const float*)d_in[0];
    const float* conv_w = (const float*)d_in[1];
    const float* conv_b = (const float*)d_in[2];
    const float* g1     = (const float*)d_in[3];
    const float* b1     = (const float*)d_in[4];
    const float* qkv_w  = (const float*)d_in[5];
    const float* qkv_b  = (const float*)d_in[6];
    const float* proj_w = (const float*)d_in[7];
    const float* proj_b = (const float*)d_in[8];
    const float* g2     = (const float*)d_in[9];
    const float* b2     = (const float*)d_in[10];
    const float* ffn_w1 = (const float*)d_in[11];
    const float* ffn_b1 = (const float*)d_in[12];
    const float* ffn_w2 = (const float*)d_in[13];
    const float* ffn_b2 = (const float*)d_in[14];
    const float* g3     = (const float*)d_in[15];
    const float* b3     = (const float*)d_in[16];
    float* out = (float*)d_out;

    __half *xpad, *wcT, *qkvT, *projT, *ffn1T, *ffn2T, *x1h, *x2h, *qkvh, *attnh, *ffnhh;
    float *conv, *x1, *proj, *x2, *ffn2;
    cudaGetSymbolAddress((void**)&xpad,  g_xpad);
    cudaGetSymbolAddress((void**)&wcT,   g_wcT);
    cudaGetSymbolAddress((void**)&qkvT,  g_qkvT);
    cudaGetSymbolAddress((void**)&projT, g_projT);
    cudaGetSymbolAddress((void**)&ffn1T, g_ffn1T);
    cudaGetSymbolAddress((void**)&ffn2T, g_ffn2T);
    cudaGetSymbolAddress((void**)&x1h,   g_x1h);
    cudaGetSymbolAddress((void**)&x2h,   g_x2h);
    cudaGetSymbolAddress((void**)&qkvh,  g_qkvh);
    cudaGetSymbolAddress((void**)&attnh, g_attnh);
    cudaGetSymbolAddress((void**)&ffnhh, g_ffnhh);
    cudaGetSymbolAddress((void**)&conv,  g_conv);
    cudaGetSymbolAddress((void**)&x1,    g_x1);
    cudaGetSymbolAddress((void**)&proj,  g_proj);
    cudaGetSymbolAddress((void**)&x2,    g_x2);
    cudaGetSymbolAddress((void**)&ffn2,  g_ffn2);

    cudaFuncSetAttribute(hgemm_kernel<1, 0>,
                         cudaFuncAttributeMaxDynamicSharedMemorySize, GEMM_SMEM);
    cudaFuncSetAttribute(hgemm_kernel<1, 1>,
                         cudaFuncAttributeMaxDynamicSharedMemorySize, GEMM_SMEM);
    cudaFuncSetAttribute(hgemm_kernel<2, 1>,
                         cudaFuncAttributeMaxDynamicSharedMemorySize, GEMM_SMEM);

    {
        int total = BDIM * (T_SEQ + 2) * CDIM;
        pad_kernel<<<(total + 255) / 256, 256>>>(x, xpad);
    }
    wconvT_kernel<<<(CDIM * 3 * CDIM + 255) / 256, 256>>>(conv_w, wcT);
    transpose_kernel<<<dim3(3 * CDIM / 32, CDIM / 32), dim3(32, 8)>>>(qkv_w, qkvT, CDIM, 3 * CDIM);
    transpose_kernel<<<dim3(CDIM / 32, CDIM / 32), dim3(32, 8)>>>(proj_w, projT, CDIM, CDIM);
    transpose_kernel<<<dim3(2 * CDIM / 32, CDIM / 32), dim3(32, 8)>>>(ffn_w1, ffn1T, CDIM, 2 * CDIM);
    transpose_kernel<<<dim3(CDIM / 32, 2 * CDIM / 32), dim3(32, 8)>>>(ffn_w2, ffn2T, 2 * CDIM, CDIM);

    // conv as GEMM: per batch M=2048, N=512, K=1536 (overlapping A rows)
    hgemm_kernel<1, 0><<<dim3(4, 16, 2), 256, GEMM_SMEM>>>(
        xpad, CDIM, (long long)(T_SEQ + 2) * CDIM,
        wcT, 3 * CDIM,
        conv, CDIM, (long long)T_SEQ * CDIM,
        3 * CDIM, conv_b);

    add_ln_kernel<<<BT, 128>>>(x, conv, g1, b1, x1, x1h);

    // qkv: M=4096, N=1536, K=512, fp16 out
    hgemm_kernel<1, 1><<<dim3(12, 32, 1), 256, GEMM_SMEM>>>(
        x1h, CDIM, 0, qkvT, CDIM, qkvh, 3 * CDIM, 0, CDIM, qkv_b);

    // fp16 causal flash attention
    flash_attn_h_kernel<<<dim3(T_SEQ / 64, BDIM * HNUM), 128>>>(qkvh, attnh);

    // proj: M=4096, N=512, K=512
    hgemm_kernel<1, 0><<<dim3(4, 32, 1), 256, GEMM_SMEM>>>(
        attnh, CDIM, 0, projT, CDIM, proj, CDIM, 0, CDIM, proj_b);

    add_ln_kernel<<<BT, 128>>>(x1, proj, g2, b2, x2, x2h);

    // ffn1: M=4096, N=1024, K=512, relu, fp16 out
    hgemm_kernel<2, 1><<<dim3(8, 32, 1), 256, GEMM_SMEM>>>(
        x2h, CDIM, 0, ffn1T, CDIM, ffnhh, 2 * CDIM, 0, CDIM, ffn_b1);

    // ffn2: M=4096, N=512, K=1024
    hgemm_kernel<1, 0><<<dim3(4, 32, 1), 256, GEMM_SMEM>>>(
        ffnhh, 2 * CDIM, 0, ffn2T, 2 * CDIM, ffn2, CDIM, 0, 2 * CDIM, ffn_b2);

    add_ln_kernel<<<BT, 128>>>(x2, ffn2, g3, b3, out, (__half*)nullptr);
}

// round 8
// speedup vs baseline: 5.2321x; 1.1266x over previous
#include <cuda_runtime.h>
#include <cuda_fp16.h>
#include <cstdint>

// Problem constants
#define T_SEQ 2048
#define CDIM  512
#define BDIM  2
#define HNUM  8
#define HD    64
#define BT    (BDIM * T_SEQ)

// ---------------- scratch (device globals; no allocation allowed) ----------
__device__ __half g_xpad [BDIM * (T_SEQ + 2) * CDIM];
__device__ __half g_wcT  [CDIM * 3 * CDIM];     // [o][k*512+i]
__device__ __half g_qkvT [3 * CDIM * CDIM];     // [1536][512]
__device__ __half g_projT[CDIM * CDIM];         // [512][512]
__device__ __half g_ffn1T[2 * CDIM * CDIM];     // [1024][512]
__device__ __half g_ffn2T[CDIM * 2 * CDIM];     // [512][1024]
__device__ __half g_x1h  [BT * CDIM];
__device__ __half g_x2h  [BT * CDIM];
__device__ __half g_qkvh [BT * 3 * CDIM];
__device__ __half g_attnh[BT * CDIM];
__device__ __half g_ffnhh[BT * 2 * CDIM];
__device__ float  g_conv [BT * CDIM];
__device__ float  g_x1   [BT * CDIM];
__device__ float  g_proj [BT * CDIM];
__device__ float  g_x2   [BT * CDIM];
__device__ float  g_ffn2 [BT * CDIM];

// ---------------- small prep kernels ---------------------------------------
__global__ void pad_kernel(const float* __restrict__ x, __half* __restrict__ xpad) {
    int idx = blockIdx.x * blockDim.x + threadIdx.x;
    const int total = BDIM * (T_SEQ + 2) * CDIM;
    if (idx >= total) return;
    int c = idx % CDIM;
    int t = (idx / CDIM) % (T_SEQ + 2);
    int b = idx / (CDIM * (T_SEQ + 2));
    float v = (t < 2) ? 0.0f : x[((long long)b * T_SEQ + (t - 2)) * CDIM + c];
    xpad[idx] = __float2half_rn(v);
}

// conv_w OIH [o][i][k] -> wcT[o][k*512+i]  (B^T for the conv GEMM)
__global__ void wconvT_kernel(const float* __restrict__ w, __half* __restrict__ outp) {
    int idx = blockIdx.x * blockDim.x + threadIdx.x;
    const int total = CDIM * 3 * CDIM;
    if (idx >= total) return;
    int o = idx / (3 * CDIM);
    int r = idx % (3 * CDIM);
    int k = r / CDIM;
    int i = r % CDIM;
    outp[idx] = __float2half_rn(w[((long long)o * CDIM + i) * 3 + k]);
}

// all 4 weight transposes [K][N] fp32 -> [N][K] fp16 in one launch.
// grid (48, 32, 4); out-of-range tiles exit.
__global__ void transpose_all_kernel(const float* __restrict__ qkv_w,
                                     const float* __restrict__ proj_w,
                                     const float* __restrict__ ffn_w1,
                                     const float* __restrict__ ffn_w2,
                                     __half* __restrict__ qkvT,
                                     __half* __restrict__ projT,
                                     __half* __restrict__ ffn1T,
                                     __half* __restrict__ ffn2T) {
    const float* in;
    __half* outp;
    int K, N;
    switch (blockIdx.z) {
        case 0: in = qkv_w;  outp = qkvT;  K = 512;  N = 1536; break;
        case 1: in = proj_w; outp = projT; K = 512;  N = 512;  break;
        case 2: in = ffn_w1; outp = ffn1T; K = 512;  N = 1024; break;
        default: in = ffn_w2; outp = ffn2T; K = 1024; N = 512; break;
    }
    int bx = blockIdx.x * 32, by = blockIdx.y * 32;
    if (bx >= N || by >= K) return;

    __shared__ float tile[32][33];
    #pragma unroll
    for (int j = 0; j < 32; j += 8)
        tile[threadIdx.y + j][threadIdx.x] =
            in[(long long)(by + threadIdx.y + j) * N + bx + threadIdx.x];
    __syncthreads();
    #pragma unroll
    for (int j = 0; j < 32; j += 8)
        outp[(long long)(bx + threadIdx.y + j) * K + by + threadIdx.x] =
            __float2half_rn(tile[threadIdx.x][threadIdx.y + j]);
}

// ---------------- fused residual add + LayerNorm (dual fp32/fp16 out) -------
__global__ void add_ln_kernel(const float* __restrict__ a, const float* __restrict__ r,
                              const float* __restrict__ g, const float* __restrict__ be,
                              float* __restrict__ out, __half* __restrict__ outh) {
    __shared__ float sh[4];
    int row = blockIdx.x;
    int tid = threadIdx.x;
    const float4 va = ((const float4*)(a + (long long)row * CDIM))[tid];
    const float4 vr = ((const float4*)(r + (long long)row * CDIM))[tid];
    float x0 = va.x + vr.x, x1 = va.y + vr.y, x2 = va.z + vr.z, x3 = va.w + vr.w;

    float s = x0 + x1 + x2 + x3;
    #pragma unroll
    for (int o = 16; o; o >>= 1) s += __shfl_xor_sync(0xffffffffu, s, o);
    if ((tid & 31) == 0) sh[tid >> 5] = s;
    __syncthreads();
    float mean = (sh[0] + sh[1] + sh[2] + sh[3]) * (1.0f / CDIM);
    __syncthreads();

    float d0 = x0 - mean, d1 = x1 - mean, d2 = x2 - mean, d3 = x3 - mean;
    float ss = d0 * d0 + d1 * d1 + d2 * d2 + d3 * d3;
    #pragma unroll
    for (int o = 16; o; o >>= 1) ss += __shfl_xor_sync(0xffffffffu, ss, o);
    if ((tid & 31) == 0) sh[tid >> 5] = ss;
    __syncthreads();
    float var = (sh[0] + sh[1] + sh[2] + sh[3]) * (1.0f / CDIM);
    float rs = rsqrtf(var + 1e-5f);

    float4 vg = ((const float4*)g)[tid];
    float4 vb = ((const float4*)be)[tid];
    float4 o4;
    o4.x = d0 * rs * vg.x + vb.x;
    o4.y = d1 * rs * vg.y + vb.y;
    o4.z = d2 * rs * vg.z + vb.z;
    o4.w = d3 * rs * vg.w + vb.w;
    ((float4*)(out + (long long)row * CDIM))[tid] = o4;
    if (outh) {
        __half2 h0 = __floats2half2_rn(o4.x, o4.y);
        __half2 h1 = __floats2half2_rn(o4.z, o4.w);
        *(uint2*)(outh + (long long)row * CDIM + tid * 4) =
            make_uint2(*(uint32_t*)&h0, *(uint32_t*)&h1);
    }
}

// ---------------- mma / ldmatrix helpers -------------------------------------
__device__ __forceinline__ void mma_f16(float c[4], uint32_t a0, uint32_t a1,
                                        uint32_t a2, uint32_t a3,
                                        uint32_t b0, uint32_t b1) {
    asm volatile(
        "mma.sync.aligned.m16n8k16.row.col.f32.f16.f16.f32 "
        "{%0,%1,%2,%3}, {%4,%5,%6,%7}, {%8,%9}, {%0,%1,%2,%3};"
        : "+f"(c[0]), "+f"(c[1]), "+f"(c[2]), "+f"(c[3])
        : "r"(a0), "r"(a1), "r"(a2), "r"(a3), "r"(b0), "r"(b1));
}

__device__ __forceinline__ void ldsm_x4(uint32_t& r0, uint32_t& r1,
                                        uint32_t& r2, uint32_t& r3, uint32_t addr) {
    asm volatile("ldmatrix.sync.aligned.m8n8.x4.shared.b16 {%0,%1,%2,%3}, [%4];"
                 : "=r"(r0), "=r"(r1), "=r"(r2), "=r"(r3) : "r"(addr));
}

#define CP16(dst, src) \
    asm volatile("cp.async.cg.shared.global [%0], [%1], 16;" :: "r"(dst), "l"(src))
#define CP_COMMIT() asm volatile("cp.async.commit_group;")
#define CP_WAIT(n)  asm volatile("cp.async.wait_group %0;" :: "n"(n))

// ---------------- fp16 TC GEMM: BK=64, ldmatrix, 3-stage, 2 CTAs/SM ----------
// C[M,N] = A[M,K] @ Bt[N,K]^T (+bias,+relu). CTA 128x128, 256 thr,
// warp tile 64x32 (m16n8k16). Tiles [128 rows][72 halves] (144B stride:
// 16B-aligned; ldmatrix row banks 4r mod 32 -> conflict-free).
#define HROW 72
#define RBYTES 144
#define ABYTES (128 * RBYTES)         // 18432 B
#define STG_BYTES (2 * ABYTES)        // 36864 B
#define GSTAGES 3
#define GEMM_SMEM (GSTAGES * STG_BYTES)   // 110592 B

__device__ __forceinline__ void load_tile_h(uint32_t sbase,
                                            const __half* __restrict__ gA, int lda,
                                            const __half* __restrict__ gB, int ldb,
                                            int tid) {
    #pragma unroll
    for (int i = 0; i < 4; i++) {
        int u = tid + i * 256;               // 1024 : 128 rows x 8 x 16B
        int row = u >> 3, c = u & 7;
        CP16(sbase + row * RBYTES + c * 16, gA + (long long)row * lda + c * 8);
    }
    #pragma unroll
    for (int i = 0; i < 4; i++) {
        int u = tid + i * 256;
        int row = u >> 3, c = u & 7;
        CP16(sbase + ABYTES + row * RBYTES + c * 16, gB + (long long)row * ldb + c * 8);
    }
}

template <int ACT, int OUTH>
__global__ __launch_bounds__(256, 2)
void hgemm_kernel(const __half* __restrict__ A, int lda, long long strideA,
                  const __half* __restrict__ Bt, int ldb,
                  void* __restrict__ Cv, int ldc, long long strideC,
                  int K, const float* __restrict__ bias) {
    A += (long long)blockIdx.z * strideA;

    extern __shared__ __half smh[];
    const int tid = threadIdx.x;
    const int lane = tid & 31;
    const int warp = tid >> 5;
    const int warpM = warp >> 2;
    const int warpN = warp & 3;
    const int tg = lane & 3;
    const int gid = lane >> 2;

    uint32_t sbase;
    asm("{ .reg .u64 t; cvta.to.shared.u64 t, %1; cvt.u32.u64 %0, t; }"
        : "=r"(sbase) : "l"(smh));

    float acc[4][4][4];
    #pragma unroll
    for (int i = 0; i < 4; i++)
        #pragma unroll
        for (int j = 0; j < 4; j++)
            #pragma unroll
            for (int q = 0; q < 4; q++) acc[i][j][q] = 0.0f;

    // ldmatrix lane-address components (constant across iterations)
    const int aRow = (lane & 15);                 // rows m+0..15
    const int aKoff = (lane >> 4) << 4;           // 0 / 16 bytes
    const int bLocal = lane & 7;
    const int bSel = (lane >> 3) & 3;
    const int bNsub = (bSel >> 1);                // 0/1 within ni-pair
    const int bKoff = (bSel & 1) * 16;

    const __half* Ag = A + (long long)blockIdx.y * 128 * lda;
    const __half* Bg = Bt + (long long)blockIdx.x * 128 * ldb;
    const int ntile = K >> 6;                     // BK = 64

    #pragma unroll
    for (int p = 0; p < GSTAGES - 1; p++) {
        load_tile_h(sbase + p * STG_BYTES, Ag + p * 64, lda, Bg + p * 64, ldb, tid);
        CP_COMMIT();
    }

    for (int t = 0; t < ntile; t++) {
        CP_WAIT(GSTAGES - 2);
        __syncthreads();

        int f = t + GSTAGES - 1;
        if (f < ntile)
            load_tile_h(sbase + (f % GSTAGES) * STG_BYTES, Ag + f * 64, lda,
                        Bg + f * 64, ldb, tid);
        CP_COMMIT();

        const uint32_t Ab = sbase + (t % GSTAGES) * STG_BYTES;
        const uint32_t Bb = Ab + ABYTES;

        #pragma unroll
        for (int ks = 0; ks < 4; ks++) {
            const int kbB = ks * 32;              // 16 halves per k-step
            uint32_t af[4][4], bf[4][2];
            #pragma unroll
            for (int mi = 0; mi < 4; mi++) {
                uint32_t addr = Ab + (warpM * 64 + mi * 16 + aRow) * RBYTES + kbB + aKoff;
                ldsm_x4(af[mi][0], af[mi][1], af[mi][2], af[mi][3], addr);
            }
            #pragma unroll
            for (int p = 0; p < 2; p++) {
                uint32_t addr = Bb + (warpN * 32 + (2 * p + bNsub) * 8 + bLocal) * RBYTES
                                + kbB + bKoff;
                ldsm_x4(bf[2 * p][0], bf[2 * p][1], bf[2 * p + 1][0], bf[2 * p + 1][1], addr);
            }
            #pragma unroll
            for (int mi = 0; mi < 4; mi++)
                #pragma unroll
                for (int ni = 0; ni < 4; ni++)
                    mma_f16(acc[mi][ni], af[mi][0], af[mi][1], af[mi][2], af[mi][3],
                            bf[ni][0], bf[ni][1]);
        }
        __syncthreads();
    }

    const int mbase = blockIdx.y * 128 + warpM * 64;
    const int nbase = blockIdx.x * 128 + warpN * 32;
    #pragma unroll
    for (int ni = 0; ni < 4; ni++) {
        int c0 = nbase + ni * 8 + tg * 2;
        float bv0 = 0.0f, bv1 = 0.0f;
        if (ACT > 0) { bv0 = bias[c0]; bv1 = bias[c0 + 1]; }
        #pragma unroll
        for (int mi = 0; mi < 4; mi++) {
            int r0 = mbase + mi * 16 + gid;
            float v00 = acc[mi][ni][0] + bv0;
            float v01 = acc[mi][ni][1] + bv1;
            float v10 = acc[mi][ni][2] + bv0;
            float v11 = acc[mi][ni][3] + bv1;
            if (ACT == 2) {
                v00 = fmaxf(v00, 0.0f); v01 = fmaxf(v01, 0.0f);
                v10 = fmaxf(v10, 0.0f); v11 = fmaxf(v11, 0.0f);
            }
            if (OUTH) {
                __half* C = (__half*)Cv + (long long)blockIdx.z * strideC;
                *(__half2*)(C + (long long)r0 * ldc + c0) = __floats2half2_rn(v00, v01);
                *(__half2*)(C + (long long)(r0 + 8) * ldc + c0) = __floats2half2_rn(v10, v11);
            } else {
                float* C = (float*)Cv + (long long)blockIdx.z * strideC;
                *(float2*)(C + (long long)r0 * ldc + c0) = make_float2(v00, v01);
                *(float2*)(C + (long long)(r0 + 8) * ldc + c0) = make_float2(v10, v11);
            }
        }
    }
}

// ---------------- fp16 tensor-core flash attention (causal) ------------------
#define KS_STRIDE 72
#define VT_STRIDE 76

__global__ __launch_bounds__(128)
void flash_attn_h_kernel(const __half* __restrict__ qkv, __half* __restrict__ out) {
    __shared__ __half Ks[64 * KS_STRIDE];
    __shared__ __half Vt[64 * VT_STRIDE];

    const int qb = (gridDim.x - 1) - blockIdx.x;
    const int bh = blockIdx.y;
    const int b = bh >> 3, h = bh & 7;
    const int tid = threadIdx.x;
    const int lane = tid & 31;
    const int warp = tid >> 5;
    const int g = lane >> 2;
    const int t = lane & 3;
    const long long rstride = 3 * CDIM;

    const __half* q0 = qkv + ((long long)(b * T_SEQ + qb * 64 + warp * 16)) * rstride + h * HD;
    uint32_t qf[4][4];
    #pragma unroll
    for (int ks = 0; ks < 4; ks++) {
        qf[ks][0] = *(const uint32_t*)(q0 + (long long)g * rstride + ks * 16 + 2 * t);
        qf[ks][1] = *(const uint32_t*)(q0 + (long long)(g + 8) * rstride + ks * 16 + 2 * t);
        qf[ks][2] = *(const uint32_t*)(q0 + (long long)g * rstride + ks * 16 + 8 + 2 * t);
        qf[ks][3] = *(const uint32_t*)(q0 + (long long)(g + 8) * rstride + ks * 16 + 8 + 2 * t);
    }

    float o[8][4];
    #pragma unroll
    for (int ni = 0; ni < 8; ni++)
        #pragma unroll
        for (int q = 0; q < 4; q++) o[ni][q] = 0.0f;
    float m0 = -1e30f, m1 = -1e30f, l0 = 0.0f, l1 = 0.0f;

    const int row0 = qb * 64 + warp * 16 + g;
    const int row1 = row0 + 8;

    for (int kb = 0; kb <= qb; kb++) {
        const __half* kbase = qkv + ((long long)(b * T_SEQ + kb * 64)) * rstride + CDIM + h * HD;
        const __half* vbase = kbase + CDIM;

        #pragma unroll
        for (int i = 0; i < 4; i++) {
            int u = tid + i * 128;
            int r = u >> 3, c = u & 7;
            *(uint4*)&Ks[r * KS_STRIDE + c * 8] =
                *(const uint4*)(kbase + (long long)r * rstride + c * 8);
        }
        #pragma unroll
        for (int i = 0; i < 2; i++) {
            int u = tid + i * 128;
            int kp = u >> 3, d8 = u & 7;
            uint4 va = *(const uint4*)(vbase + (long long)(2 * kp) * rstride + d8 * 8);
            uint4 vb = *(const uint4*)(vbase + (long long)(2 * kp + 1) * rstride + d8 * 8);
            const __half* ah = (const __half*)&va;
            const __half* bhp = (const __half*)&vb;
            #pragma unroll
            for (int j = 0; j < 8; j++)
                *(__half2*)&Vt[(d8 * 8 + j) * VT_STRIDE + 2 * kp] =
                    __halves2half2(ah[j], bhp[j]);
        }
        __syncthreads();

        float s[8][4];
        #pragma unroll
        for (int ni = 0; ni < 8; ni++) {
            s[ni][0] = s[ni][1] = s[ni][2] = s[ni][3] = 0.0f;
            const __half* kr = &Ks[(ni * 8 + g) * KS_STRIDE];
            #pragma unroll
            for (int ks = 0; ks < 4; ks++) {
                uint32_t b0 = *(const uint32_t*)(kr + ks * 16 + 2 * t);
                uint32_t b1 = *(const uint32_t*)(kr + ks * 16 + 8 + 2 * t);
                mma_f16(s[ni], qf[ks][0], qf[ks][1], qf[ks][2], qf[ks][3], b0, b1);
            }
            s[ni][0] *= 0.125f; s[ni][1] *= 0.125f;
            s[ni][2] *= 0.125f; s[ni][3] *= 0.125f;
        }

        if (kb == qb) {
            #pragma unroll
            for (int ni = 0; ni < 8; ni++) {
                int col = kb * 64 + ni * 8 + 2 * t;
                if (col > row0)     s[ni][0] = -1e30f;
                if (col + 1 > row0) s[ni][1] = -1e30f;
                if (col > row1)     s[ni][2] = -1e30f;
                if (col + 1 > row1) s[ni][3] = -1e30f;
            }
        }

        float mt0 = -1e30f, mt1 = -1e30f;
        #pragma unroll
        for (int ni = 0; ni < 8; ni++) {
            mt0 = fmaxf(mt0, fmaxf(s[ni][0], s[ni][1]));
            mt1 = fmaxf(mt1, fmaxf(s[ni][2], s[ni][3]));
        }
        mt0 = fmaxf(mt0, __shfl_xor_sync(0xffffffffu, mt0, 1));
        mt0 = fmaxf(mt0, __shfl_xor_sync(0xffffffffu, mt0, 2));
        mt1 = fmaxf(mt1, __shfl_xor_sync(0xffffffffu, mt1, 1));
        mt1 = fmaxf(mt1, __shfl_xor_sync(0xffffffffu, mt1, 2));

        float mn0 = fmaxf(m0, mt0), mn1 = fmaxf(m1, mt1);
        float corr0 = __expf(m0 - mn0), corr1 = __expf(m1 - mn1);
        m0 = mn0; m1 = mn1;

        float ps0 = 0.0f, ps1 = 0.0f;
        float p[8][4];
        #pragma unroll
        for (int ni = 0; ni < 8; ni++) {
            p[ni][0] = __expf(s[ni][0] - mn0);
            p[ni][1] = __expf(s[ni][1] - mn0);
            p[ni][2] = __expf(s[ni][2] - mn1);
            p[ni][3] = __expf(s[ni][3] - mn1);
            ps0 += p[ni][0] + p[ni][1];
            ps1 += p[ni][2] + p[ni][3];
        }
        ps0 += __shfl_xor_sync(0xffffffffu, ps0, 1);
        ps0 += __shfl_xor_sync(0xffffffffu, ps0, 2);
        ps1 += __shfl_xor_sync(0xffffffffu, ps1, 1);
        ps1 += __shfl_xor_sync(0xffffffffu, ps1, 2);
        l0 = l0 * corr0 + ps0;
        l1 = l1 * corr1 + ps1;

        uint32_t pf[4][4];
        #pragma unroll
        for (int j = 0; j < 4; j++) {
            __half2 h0 = __floats2half2_rn(p[2 * j][0],     p[2 * j][1]);
            __half2 h1 = __floats2half2_rn(p[2 * j][2],     p[2 * j][3]);
            __half2 h2 = __floats2half2_rn(p[2 * j + 1][0], p[2 * j + 1][1]);
            __half2 h3 = __floats2half2_rn(p[2 * j + 1][2], p[2 * j + 1][3]);
            pf[j][0] = *(uint32_t*)&h0;
            pf[j][1] = *(uint32_t*)&h1;
            pf[j][2] = *(uint32_t*)&h2;
            pf[j][3] = *(uint32_t*)&h3;
        }

        #pragma unroll
        for (int ni = 0; ni < 8; ni++) {
            o[ni][0] *= corr0;
            o[ni][1] *= corr0;
            o[ni][2] *= corr1;
            o[ni][3] *= corr1;
        }

        #pragma unroll
        for (int ni = 0; ni < 8; ni++) {
            const __half* vr = &Vt[(ni * 8 + g) * VT_STRIDE];
            #pragma unroll
            for (int j = 0; j < 4; j++) {
                uint32_t b0 = *(const uint32_t*)(vr + j * 16 + 2 * t);
                uint32_t b1 = *(const uint32_t*)(vr + j * 16 + 8 + 2 * t);
                mma_f16(o[ni], pf[j][0], pf[j][1], pf[j][2], pf[j][3], b0, b1);
            }
        }
        __syncthreads();
    }

    float inv0 = 1.0f / l0, inv1 = 1.0f / l1;
    __half* obase = out + ((long long)(b * T_SEQ)) * CDIM + h * HD;
    #pragma unroll
    for (int ni = 0; ni < 8; ni++) {
        int col = ni * 8 + 2 * t;
        *(__half2*)(obase + (long long)row0 * CDIM + col) =
            __floats2half2_rn(o[ni][0] * inv0, o[ni][1] * inv0);
        *(__half2*)(obase + (long long)row1 * CDIM + col) =
            __floats2half2_rn(o[ni][2] * inv1, o[ni][3] * inv1);
    }
}

// ---------------- launch -----------------------------------------------------
extern "C" void kernel_launch(void* const* d_in, const int* in_sizes, int n_in,
                              void* d_out, int out_size) {
    const float* x      = (const float*)d_in[0];
    const float* conv_w = (const float*)d_in[1];
    const float* conv_b = (const float*)d_in[2];
    const float* g1     = (const float*)d_in[3];
    const float* b1     = (const float*)d_in[4];
    const float* qkv_w  = (const float*)d_in[5];
    const float* qkv_b  = (const float*)d_in[6];
    const float* proj_w = (const float*)d_in[7];
    const float* proj_b = (const float*)d_in[8];
    const float* g2     = (const float*)d_in[9];
    const float* b2     = (const float*)d_in[10];
    const float* ffn_w1 = (const float*)d_in[11];
    const float* ffn_b1 = (const float*)d_in[12];
    const float* ffn_w2 = (const float*)d_in[13];
    const float* ffn_b2 = (const float*)d_in[14];
    const float* g3     = (const float*)d_in[15];
    const float* b3     = (const float*)d_in[16];
    float* out = (float*)d_out;

    __half *xpad, *wcT, *qkvT, *projT, *ffn1T, *ffn2T, *x1h, *x2h, *qkvh, *attnh, *ffnhh;
    float *conv, *x1, *proj, *x2, *ffn2;
    cudaGetSymbolAddress((void**)&xpad,  g_xpad);
    cudaGetSymbolAddress((void**)&wcT,   g_wcT);
    cudaGetSymbolAddress((void**)&qkvT,  g_qkvT);
    cudaGetSymbolAddress((void**)&projT, g_projT);
    cudaGetSymbolAddress((void**)&ffn1T, g_ffn1T);
    cudaGetSymbolAddress((void**)&ffn2T, g_ffn2T);
    cudaGetSymbolAddress((void**)&x1h,   g_x1h);
    cudaGetSymbolAddress((void**)&x2h,   g_x2h);
    cudaGetSymbolAddress((void**)&qkvh,  g_qkvh);
    cudaGetSymbolAddress((void**)&attnh, g_attnh);
    cudaGetSymbolAddress((void**)&ffnhh, g_ffnhh);
    cudaGetSymbolAddress((void**)&conv,  g_conv);
    cudaGetSymbolAddress((void**)&x1,    g_x1);
    cudaGetSymbolAddress((void**)&proj,  g_proj);
    cudaGetSymbolAddress((void**)&x2,    g_x2);
    cudaGetSymbolAddress((void**)&ffn2,  g_ffn2);

    cudaFuncSetAttribute(hgemm_kernel<1, 0>,
                         cudaFuncAttributeMaxDynamicSharedMemorySize, GEMM_SMEM);
    cudaFuncSetAttribute(hgemm_kernel<1, 1>,
                         cudaFuncAttributeMaxDynamicSharedMemorySize, GEMM_SMEM);
    cudaFuncSetAttribute(hgemm_kernel<2, 1>,
                         cudaFuncAttributeMaxDynamicSharedMemorySize, GEMM_SMEM);

    {
        int total = BDIM * (T_SEQ + 2) * CDIM;
        pad_kernel<<<(total + 255) / 256, 256>>>(x, xpad);
    }
    wconvT_kernel<<<(CDIM * 3 * CDIM + 255) / 256, 256>>>(conv_w, wcT);
    transpose_all_kernel<<<dim3(48, 32, 4), dim3(32, 8)>>>(
        qkv_w, proj_w, ffn_w1, ffn_w2, qkvT, projT, ffn1T, ffn2T);

    // conv as GEMM: per batch M=2048, N=512, K=1536 (overlapping A rows)
    hgemm_kernel<1, 0><<<dim3(4, 16, 2), 256, GEMM_SMEM>>>(
        xpad, CDIM, (long long)(T_SEQ + 2) * CDIM,
        wcT, 3 * CDIM,
        conv, CDIM, (long long)T_SEQ * CDIM,
        3 * CDIM, conv_b);

    add_ln_kernel<<<BT, 128>>>(x, conv, g1, b1, x1, x1h);

    // qkv: M=4096, N=1536, K=512, fp16 out
    hgemm_kernel<1, 1><<<dim3(12, 32, 1), 256, GEMM_SMEM>>>(
        x1h, CDIM, 0, qkvT, CDIM, qkvh, 3 * CDIM, 0, CDIM, qkv_b);

    // fp16 causal flash attention
    flash_attn_h_kernel<<<dim3(T_SEQ / 64, BDIM * HNUM), 128>>>(qkvh, attnh);

    // proj: M=4096, N=512, K=512
    hgemm_kernel<1, 0><<<dim3(4, 32, 1), 256, GEMM_SMEM>>>(
        attnh, CDIM, 0, projT, CDIM, proj, CDIM, 0, CDIM, proj_b);

    add_ln_kernel<<<BT, 128>>>(x1, proj, g2, b2, x2, x2h);

    // ffn1: M=4096, N=1024, K=512, relu, fp16 out
    hgemm_kernel<2, 1><<<dim3(8, 32, 1), 256, GEMM_SMEM>>>(
        x2h, CDIM, 0, ffn1T, CDIM, ffnhh, 2 * CDIM, 0, CDIM, ffn_b1);

    // ffn2: M=4096, N=512, K=1024
    hgemm_kernel<1, 0><<<dim3(4, 32, 1), 256, GEMM_SMEM>>>(
        ffnhh, 2 * CDIM, 0, ffn2T, 2 * CDIM, ffn2, CDIM, 0, 2 * CDIM, ffn_b2);

    add_ln_kernel<<<BT, 128>>>(x2, ffn2, g3, b3, out, (__half*)nullptr);
}